// round 14
// baseline (speedup 1.0000x reference)
#include <cuda_runtime.h>
#include <cuda_bf16.h>
#include <cstdint>

#define B_  4
#define N_  4096
#define M1_ 2048
#define M2_ 512
#define F1_ 64
#define F2_ 128
#define F3_ 1024
#define LF_ 64
#define MAXNBR 128

// grid constants (fixed range, row-major cells) shared by FPS and SA pruning
#define GRID_LO   (-18.0f)
#define GRID_INV  (16.0f / 36.0f)

// ---------------- device scratch ----------------
__device__ float g_p1  [B_ * N_  * F1_];
__device__ float g_h1  [B_ * M1_ * F1_];
__device__ float g_ctr1[B_ * M1_ * 2];
__device__ float g_p2  [B_ * M1_ * F2_];
__device__ float g_h2  [B_ * M2_ * F2_];
__device__ float g_ctr2[B_ * M2_ * 2];
__device__ float g_pmax[B_ * 8 * F3_];
// exported bucket sort (level 0: x points, level 1: ctr1 points)
__device__ float          g_sxl[2][B_][N_];
__device__ float          g_syl[2][B_][N_];
__device__ unsigned short g_sil[2][B_][N_];
__device__ int            g_cel[2][B_][256];

// ------ fused: lf = tanh(tanh(x W1+b1) W2+b2);  p1 = [lf,z] @ c1W[:65]+c1b
__global__ void lfp1_kernel(const float* __restrict__ x, const float* __restrict__ zones,
                            const float* __restrict__ W1, const float* __restrict__ b1,
                            const float* __restrict__ W2, const float* __restrict__ b2,
                            const float* __restrict__ c1W, const float* __restrict__ c1b,
                            float* __restrict__ lf_out) {
    __shared__ float sW2[64 * 64];
    __shared__ float sWc[65 * 64];
    __shared__ float sW1[2 * 64];
    __shared__ float sb1[64], sb2[64], sbc[64];
    __shared__ float st1[64], slf[64];
    int tid = threadIdx.x;  // 64
    for (int i = tid; i < 64 * 64; i += 64) sW2[i] = W2[i];
    for (int i = tid; i < 65 * 64; i += 64) sWc[i] = c1W[i];
    sW1[tid] = W1[tid]; sW1[64 + tid] = W1[64 + tid];
    sb1[tid] = b1[tid]; sb2[tid] = b2[tid]; sbc[tid] = c1b[tid];
    __syncthreads();
    int row0 = blockIdx.x * 32;
    for (int r = 0; r < 32; r++) {
        int row = row0 + r;
        float x0 = x[row * 2], x1 = x[row * 2 + 1];
        float t1 = tanhf(x0 * sW1[tid] + x1 * sW1[64 + tid] + sb1[tid]);
        st1[tid] = t1;
        __syncthreads();
        float acc = sb2[tid];
#pragma unroll
        for (int c = 0; c < 64; c++) acc = fmaf(st1[c], sW2[c * 64 + tid], acc);
        float lf = tanhf(acc);
        lf_out[row * 64 + tid] = lf;
        slf[tid] = lf;
        __syncthreads();
        float z = zones[row];
        float acc2 = fmaf(z, sWc[64 * 64 + tid], sbc[tid]);
#pragma unroll
        for (int c = 0; c < 64; c++) acc2 = fmaf(slf[c], sWc[c * 64 + tid], acc2);
        g_p1[row * 64 + tid] = acc2;
        __syncthreads();
    }
}

// ---------------- FPS: bucketed + warp bbox prune + redundant redux merge --
// DUAL=1 (FPS level 1): T=512 but each warp owns TWO 128-pt regions taken
// from ANTIPODAL halves of the spatially sorted array, so both regions are
// rarely active for the same pick (fixes R11's adjacent-region serialization)
// while keeping the cheap 16-warp merge/barrier chain.
// DUAL=0: single region per warp (R13 form).
// Merge tuple split as float[32] + ushort[32] (R13). Exact vs jnp.argmax:
// skipped region updates are provably no-ops (bbox lower bound >= cached
// region max); all reductions/combines are (max value, min ORIGINAL index)
// -> identical first-occurrence winner. Exports bucket sort for SA pruning.
template <int T, int P, int DUAL, int N, int M, int LEVEL>
__global__ __launch_bounds__(T, 1) void fps_kernel(const float* __restrict__ pos_in) {
    const unsigned FULL = 0xFFFFFFFFu;
    const int PH = DUAL ? (P / 2) : P;
    int b = blockIdx.x;
    int tid = threadIdx.x;
    int wid = tid >> 5, lane = tid & 31;
    const float2* p = (LEVEL == 0) ? (const float2*)(pos_in + (size_t)b * N * 2)
                                   : (const float2*)(g_ctr1 + (size_t)b * N * 2);
    float* cout = (LEVEL == 0) ? (g_ctr1 + (size_t)b * M * 2)
                               : (g_ctr2 + (size_t)b * M * 2);

    __shared__ float2 sxy[N];               // ORIGINAL order (winner lookup)
    __shared__ float spx[N], spy[N];        // sorted (init only)
    __shared__ unsigned short ssidx[N];     // sorted -> original idx
    __shared__ int counts[256], offs[256], cursor[256];
    __shared__ float          sVv[2][32];   // per-warp max value (zero-padded)
    __shared__ unsigned short sVi[2][32];   // per-warp argmin idx (0xFFFF-padded)

    // ---- load raw, publish original-order table ----
    float rx[P], ry[P];
    int cid[P];
#pragma unroll
    for (int k = 0; k < P; k++) {
        float2 v = p[tid + k * T];
        rx[k] = v.x; ry[k] = v.y;
        sxy[tid + k * T] = v;
    }
    if (tid < 256) counts[tid] = 0;
    if (tid < 64) { sVv[tid >> 5][tid & 31] = 0.0f; sVi[tid >> 5][tid & 31] = 0xFFFFu; }
    __syncthreads();
#pragma unroll
    for (int k = 0; k < P; k++) {
        int cx = (int)fminf(fmaxf((rx[k] - GRID_LO) * GRID_INV, 0.f), 15.f);
        int cy = (int)fminf(fmaxf((ry[k] - GRID_LO) * GRID_INV, 0.f), 15.f);
        cid[k] = cy * 16 + cx;
        atomicAdd(&counts[cid[k]], 1);
    }
    __syncthreads();
    if (tid < 256) offs[tid] = counts[tid];
    __syncthreads();
    for (int d = 1; d < 256; d <<= 1) {
        int v = 0;
        if (tid < 256 && tid >= d) v = offs[tid - d];
        __syncthreads();
        if (tid < 256 && tid >= d) offs[tid] += v;
        __syncthreads();
    }
    if (tid < 256) cursor[tid] = offs[tid] - counts[tid];
    __syncthreads();
#pragma unroll
    for (int k = 0; k < P; k++) {
        int pos = atomicAdd(&cursor[cid[k]], 1);
        spx[pos] = rx[k]; spy[pos] = ry[k];
        ssidx[pos] = (unsigned short)(tid + k * T);
    }
    __syncthreads();

    // ---- export bucket sort for SA pruning (one-time) ----
    for (int i = tid; i < N; i += T) {
        g_sxl[LEVEL][b][i] = spx[i];
        g_syl[LEVEL][b][i] = spy[i];
        g_sil[LEVEL][b][i] = ssidx[i];
    }
    if (tid < 256) g_cel[LEVEL][b][tid] = offs[tid];  // inclusive prefix = cell end

    // ---- registers: region(s) + bbox(es) ----
    float pxA[PH], pyA[PH], mdA[PH];
    unsigned siA[PH];
    float ax0 = 1e30f, ax1 = -1e30f, ay0 = 1e30f, ay1 = -1e30f;
    int baseA = tid * PH;
#pragma unroll
    for (int k = 0; k < PH; k++) {
        pxA[k] = spx[baseA + k]; pyA[k] = spy[baseA + k];
        siA[k] = (unsigned)ssidx[baseA + k];
        mdA[k] = 1e10f;
        ax0 = fminf(ax0, pxA[k]); ax1 = fmaxf(ax1, pxA[k]);
        ay0 = fminf(ay0, pyA[k]); ay1 = fmaxf(ay1, pyA[k]);
    }
    float pxB[DUAL ? PH : 1], pyB[DUAL ? PH : 1], mdB[DUAL ? PH : 1];
    unsigned siB[DUAL ? PH : 1];
    float bx0 = 1e30f, bx1 = -1e30f, by0 = 1e30f, by1 = -1e30f;
    if (DUAL) {
        int baseB = N / 2 + tid * PH;   // ANTIPODAL half
#pragma unroll
        for (int k = 0; k < PH; k++) {
            pxB[k] = spx[baseB + k]; pyB[k] = spy[baseB + k];
            siB[k] = (unsigned)ssidx[baseB + k];
            mdB[k] = 1e10f;
            bx0 = fminf(bx0, pxB[k]); bx1 = fmaxf(bx1, pxB[k]);
            by0 = fminf(by0, pyB[k]); by1 = fmaxf(by1, pyB[k]);
        }
    }
#pragma unroll
    for (int o = 16; o > 0; o >>= 1) {
        ax0 = fminf(ax0, __shfl_xor_sync(FULL, ax0, o));
        ax1 = fmaxf(ax1, __shfl_xor_sync(FULL, ax1, o));
        ay0 = fminf(ay0, __shfl_xor_sync(FULL, ay0, o));
        ay1 = fmaxf(ay1, __shfl_xor_sync(FULL, ay1, o));
        if (DUAL) {
            bx0 = fminf(bx0, __shfl_xor_sync(FULL, bx0, o));
            bx1 = fmaxf(bx1, __shfl_xor_sync(FULL, bx1, o));
            by0 = fminf(by0, __shfl_xor_sync(FULL, by0, o));
            by1 = fmaxf(by1, __shfl_xor_sync(FULL, by1, o));
        }
    }
    __syncthreads();

    float2 c0 = sxy[0];
    float lx = c0.x, ly = c0.y;
    if (tid == 0) { cout[0] = lx; cout[1] = ly; }

    // cached per-region warp tuples (uniform across lanes)
    float wvAf = 1e10f; unsigned wvA = __float_as_uint(1e10f), wiA = 0u;
    float wvBf = 1e10f; unsigned wvB = __float_as_uint(1e10f), wiB = 0u;

    for (int t = 1; t < M; t++) {
        float exA = fmaxf(fmaxf(ax0 - lx, lx - ax1), 0.f);
        float eyA = fmaxf(fmaxf(ay0 - ly, ly - ay1), 0.f);
        float lbA = fmaf(exA, exA, eyA * eyA);
        if (lbA < wvAf) {   // uniform per-warp branch (region A)
            float tb = -1.f;
#pragma unroll
            for (int k = 0; k < PH; k++) {
                float dx = pxA[k] - lx, dy = pyA[k] - ly;
                float d2 = fmaf(dx, dx, dy * dy);
                mdA[k] = fminf(mdA[k], d2);
                tb = fmaxf(tb, mdA[k]);
            }
            unsigned bi = 0xFFFFFFFFu;
#pragma unroll
            for (int k = 0; k < PH; k++)
                if (mdA[k] == tb && siA[k] < bi) bi = siA[k];
            unsigned vb = __float_as_uint(tb);
            unsigned wm = __reduce_max_sync(FULL, vb);
            wiA = __reduce_min_sync(FULL, (vb == wm) ? bi : 0xFFFFFFFFu);
            wvA = wm; wvAf = __uint_as_float(wm);
        }
        unsigned cv = wvA, ci = wiA;
        if (DUAL) {
            float exB = fmaxf(fmaxf(bx0 - lx, lx - bx1), 0.f);
            float eyB = fmaxf(fmaxf(by0 - ly, ly - by1), 0.f);
            float lbB = fmaf(exB, exB, eyB * eyB);
            if (lbB < wvBf) {   // uniform per-warp branch (region B)
                float tb = -1.f;
#pragma unroll
                for (int k = 0; k < PH; k++) {
                    float dx = pxB[k] - lx, dy = pyB[k] - ly;
                    float d2 = fmaf(dx, dx, dy * dy);
                    mdB[k] = fminf(mdB[k], d2);
                    tb = fmaxf(tb, mdB[k]);
                }
                unsigned bi = 0xFFFFFFFFu;
#pragma unroll
                for (int k = 0; k < PH; k++)
                    if (mdB[k] == tb && siB[k] < bi) bi = siB[k];
                unsigned vb = __float_as_uint(tb);
                unsigned wm = __reduce_max_sync(FULL, vb);
                wiB = __reduce_min_sync(FULL, (vb == wm) ? bi : 0xFFFFFFFFu);
                wvB = wm; wvBf = __uint_as_float(wm);
            }
            // combine (max value, min ORIGINAL index on tie)
            if (wvB > cv)       { cv = wvB; ci = wiB; }
            else if (wvB == cv) { ci = min(ci, wiB); }
        }
        int buf = t & 1;
        if (lane == 0) {
            sVv[buf][wid] = __uint_as_float(cv);
            sVi[buf][wid] = (unsigned short)ci;
        }
        __syncthreads();
        float v2f = sVv[buf][lane];              // pad slots: 0.0f
        unsigned i2 = (unsigned)sVi[buf][lane];  // pad slots: 0xFFFF
        unsigned v2 = __float_as_uint(v2f);
        unsigned m2 = __reduce_max_sync(FULL, v2);
        unsigned c2 = (v2 == m2) ? i2 : 0xFFFFFFFFu;
        unsigned gi = __reduce_min_sync(FULL, c2);
        float2 w = sxy[gi];          // broadcast LDS.64
        lx = w.x; ly = w.y;
        if (tid == 0) { cout[t * 2] = lx; cout[t * 2 + 1] = ly; }
    }
}

// ---------------- SA1: grid-pruned radius scan + max-aggregate ------------
__global__ void sa1_kernel(const float* __restrict__ c1W) {
    const int M = M1_, F = F1_;
    const float R = 0.5f, R2 = 0.25f;
    int i = blockIdx.x, b = blockIdx.y, tid = threadIdx.x;  // 64 threads
    __shared__ float sdx[MAXNBR], sdy[MAXNBR];
    __shared__ int   snb[MAXNBR];
    __shared__ int   scnt;
    if (tid == 0) scnt = 0;
    __syncthreads();
    float cx = g_ctr1[(b * M + i) * 2], cy = g_ctr1[(b * M + i) * 2 + 1];
    int ix0 = max(0, (int)((cx - R - GRID_LO) * GRID_INV));
    int ix1 = min(15, (int)((cx + R - GRID_LO) * GRID_INV));
    int iy0 = max(0, (int)((cy - R - GRID_LO) * GRID_INV));
    int iy1 = min(15, (int)((cy + R - GRID_LO) * GRID_INV));
    for (int gy = iy0; gy <= iy1; gy++) {
        int c0 = gy * 16 + ix0, c1 = gy * 16 + ix1;
        int s = (c0 == 0) ? 0 : g_cel[0][b][c0 - 1];
        int e = g_cel[0][b][c1];
        for (int j = s + tid; j < e; j += 64) {
            float dx = g_sxl[0][b][j] - cx;
            float dy = g_syl[0][b][j] - cy;
            float d2 = fmaf(dx, dx, dy * dy);
            if (d2 <= R2) {
                int s2 = atomicAdd(&scnt, 1);
                if (s2 < MAXNBR) {
                    snb[s2] = (int)g_sil[0][b][j];
                    sdx[s2] = dx; sdy[s2] = dy;
                }
            }
        }
    }
    __syncthreads();
    int cnt = min(scnt, MAXNBR);
    float wx = c1W[65 * 64 + tid];
    float wy = c1W[66 * 64 + tid];
    float mx = -1e9f;
    const float* pb = g_p1 + (size_t)b * N_ * F;
    int n = 0;
    for (; n + 4 <= cnt; n += 4) {
        float v0 = pb[snb[n] * F + tid];
        float v1 = pb[snb[n + 1] * F + tid];
        float v2 = pb[snb[n + 2] * F + tid];
        float v3 = pb[snb[n + 3] * F + tid];
        float m0 = fmaf(sdx[n], wx, fmaf(sdy[n], wy, v0));
        float m1 = fmaf(sdx[n + 1], wx, fmaf(sdy[n + 1], wy, v1));
        float m2 = fmaf(sdx[n + 2], wx, fmaf(sdy[n + 2], wy, v2));
        float m3 = fmaf(sdx[n + 3], wx, fmaf(sdy[n + 3], wy, v3));
        mx = fmaxf(mx, fmaxf(fmaxf(m0, m1), fmaxf(m2, m3)));
    }
    for (; n < cnt; n++) {
        float m = fmaf(sdx[n], wx, fmaf(sdy[n], wy, pb[snb[n] * F + tid]));
        mx = fmaxf(mx, m);
    }
    g_h1[((size_t)b * M + i) * F + tid] = mx;
}

// ---------------- p2[j] = h1_j @ c2W[:64] + c2b ---------------------------
__global__ void p2_kernel(const float* __restrict__ c2W, const float* __restrict__ c2b) {
    __shared__ float sW[64 * 128];
    __shared__ float sb[128];
    __shared__ float srow[64];
    int tid = threadIdx.x;  // 128
    for (int i = tid; i < 64 * 128; i += 128) sW[i] = c2W[i];
    sb[tid] = c2b[tid];
    __syncthreads();
    int row0 = blockIdx.x * 32;
    for (int r = 0; r < 32; r++) {
        int row = row0 + r;
        if (tid < 64) srow[tid] = g_h1[row * 64 + tid];
        __syncthreads();
        float acc = sb[tid];
#pragma unroll
        for (int c = 0; c < 64; c++) acc = fmaf(srow[c], sW[c * 128 + tid], acc);
        g_p2[row * 128 + tid] = acc;
        __syncthreads();
    }
}

// ---------------- SA2: grid-pruned (r=1.0 over ctr1 via FPS2's sort) ------
__global__ void sa2_kernel(const float* __restrict__ c2W) {
    const int M = M2_, F = F2_;
    const float R = 1.0f, R2 = 1.0f;
    int i = blockIdx.x, b = blockIdx.y, tid = threadIdx.x;  // 128
    __shared__ float sdx[MAXNBR], sdy[MAXNBR];
    __shared__ int   snb[MAXNBR];
    __shared__ int   scnt;
    if (tid == 0) scnt = 0;
    __syncthreads();
    float cx = g_ctr2[(b * M + i) * 2], cy = g_ctr2[(b * M + i) * 2 + 1];
    int ix0 = max(0, (int)((cx - R - GRID_LO) * GRID_INV));
    int ix1 = min(15, (int)((cx + R - GRID_LO) * GRID_INV));
    int iy0 = max(0, (int)((cy - R - GRID_LO) * GRID_INV));
    int iy1 = min(15, (int)((cy + R - GRID_LO) * GRID_INV));
    for (int gy = iy0; gy <= iy1; gy++) {
        int c0 = gy * 16 + ix0, c1 = gy * 16 + ix1;
        int s = (c0 == 0) ? 0 : g_cel[1][b][c0 - 1];
        int e = g_cel[1][b][c1];
        for (int j = s + tid; j < e; j += F) {
            float dx = g_sxl[1][b][j] - cx;
            float dy = g_syl[1][b][j] - cy;
            float d2 = fmaf(dx, dx, dy * dy);
            if (d2 <= R2) {
                int s2 = atomicAdd(&scnt, 1);
                if (s2 < MAXNBR) {
                    snb[s2] = (int)g_sil[1][b][j];
                    sdx[s2] = dx; sdy[s2] = dy;
                }
            }
        }
    }
    __syncthreads();
    int cnt = min(scnt, MAXNBR);
    float wx = c2W[64 * 128 + tid];
    float wy = c2W[65 * 128 + tid];
    float mx = -1e9f;
    const float* pb = g_p2 + (size_t)b * M1_ * F;
    int n = 0;
    for (; n + 4 <= cnt; n += 4) {
        float v0 = pb[snb[n] * F + tid];
        float v1 = pb[snb[n + 1] * F + tid];
        float v2 = pb[snb[n + 2] * F + tid];
        float v3 = pb[snb[n + 3] * F + tid];
        float m0 = fmaf(sdx[n], wx, fmaf(sdy[n], wy, v0));
        float m1 = fmaf(sdx[n + 1], wx, fmaf(sdy[n + 1], wy, v1));
        float m2 = fmaf(sdx[n + 2], wx, fmaf(sdy[n + 2], wy, v2));
        float m3 = fmaf(sdx[n + 3], wx, fmaf(sdy[n + 3], wy, v3));
        mx = fmaxf(mx, fmaxf(fmaxf(m0, m1), fmaxf(m2, m3)));
    }
    for (; n < cnt; n++) {
        float m = fmaf(sdx[n], wx, fmaf(sdy[n], wy, pb[snb[n] * F + tid]));
        mx = fmaxf(mx, m);
    }
    g_h2[((size_t)b * M + i) * F + tid] = mx;
}

// ---------------- final projection + partial max pool ---------------------
__global__ void final_partial(const float* __restrict__ W, const float* __restrict__ bias) {
    int fchunk = blockIdx.x, rchunk = blockIdx.y, b = blockIdx.z;
    int tid = threadIdx.x;  // 128
    int f = fchunk * 128 + tid;
    __shared__ float sh[64][132];
    int r0 = rchunk * 64;
    for (int e = tid; e < 64 * 130; e += 128) {
        int r = e / 130, c = e % 130;
        float v;
        if (c < 128) v = g_h2[((size_t)b * M2_ + r0 + r) * 128 + c];
        else         v = g_ctr2[(b * M2_ + r0 + r) * 2 + (c - 128)];
        sh[r][c] = v;
    }
    __syncthreads();
    float acc[64];
#pragma unroll
    for (int r = 0; r < 64; r++) acc[r] = 0.0f;
    for (int c = 0; c < 130; c++) {
        float w = W[c * 1024 + f];
#pragma unroll
        for (int r = 0; r < 64; r++) acc[r] = fmaf(sh[r][c], w, acc[r]);
    }
    float mx = acc[0];
#pragma unroll
    for (int r = 1; r < 64; r++) mx = fmaxf(mx, acc[r]);
    g_pmax[(b * 8 + rchunk) * 1024 + f] = mx + bias[f];
}

__global__ void final_reduce(float* __restrict__ gf) {
    int b = blockIdx.x, f = threadIdx.x;  // 1024
    float mx = g_pmax[(b * 8) * 1024 + f];
#pragma unroll
    for (int r = 1; r < 8; r++) mx = fmaxf(mx, g_pmax[(b * 8 + r) * 1024 + f]);
    gf[b * 1024 + f] = mx;
}

// ---------------- launch ---------------------------------------------------
extern "C" void kernel_launch(void* const* d_in, const int* in_sizes, int n_in,
                              void* d_out, int out_size) {
    const float* x     = (const float*)d_in[0];
    const float* zones = (const float*)d_in[1];
    const float* lf_W1 = (const float*)d_in[2];
    const float* lf_b1 = (const float*)d_in[3];
    const float* lf_W2 = (const float*)d_in[4];
    const float* lf_b2 = (const float*)d_in[5];
    const float* c1_W  = (const float*)d_in[6];
    const float* c1_b  = (const float*)d_in[7];
    const float* c2_W  = (const float*)d_in[8];
    const float* c2_b  = (const float*)d_in[9];
    const float* c3_W  = (const float*)d_in[10];
    const float* c3_b  = (const float*)d_in[11];

    float* lf_out = (float*)d_out;
    float* gf_out = (float*)d_out + (size_t)B_ * N_ * LF_;

    fps_kernel<512, 8, 1, N_, M1_, 0><<<B_, 512>>>(x);          // FPS L1: dual antipodal 128-pt regions
    lfp1_kernel<<<(B_ * N_) / 32, 64>>>(x, zones, lf_W1, lf_b1, lf_W2, lf_b2,
                                        c1_W, c1_b, lf_out);
    fps_kernel<512, 4, 0, M1_, M2_, 1><<<B_, 512>>>(nullptr);   // FPS L2: single region
    sa1_kernel<<<dim3(M1_, B_), 64>>>(c1_W);
    p2_kernel<<<(B_ * M1_) / 32, 128>>>(c2_W, c2_b);
    sa2_kernel<<<dim3(M2_, B_), F2_>>>(c2_W);
    final_partial<<<dim3(8, 8, B_), 128>>>(c3_W, c3_b);
    final_reduce<<<B_, 1024>>>(gf_out);
}

// round 15
// speedup vs baseline: 1.3671x; 1.3671x over previous
#include <cuda_runtime.h>
#include <cuda_bf16.h>
#include <cstdint>

#define B_  4
#define N_  4096
#define M1_ 2048
#define M2_ 512
#define F1_ 64
#define F2_ 128
#define F3_ 1024
#define LF_ 64
#define MAXNBR 128

#define GRID_LO   (-18.0f)
#define GRID_INV  (16.0f / 36.0f)

// ---------------- device scratch ----------------
__device__ float g_p1  [B_ * N_  * F1_];
__device__ float g_h1  [B_ * M1_ * F1_];
__device__ float g_ctr1[B_ * M1_ * 2];
__device__ float g_p2  [B_ * M1_ * F2_];
__device__ float g_h2  [B_ * M2_ * F2_];
__device__ float g_ctr2[B_ * M2_ * 2];
__device__ float g_pmax[B_ * 8 * F3_];
__device__ float          g_sxl[2][B_][N_];
__device__ float          g_syl[2][B_][N_];
__device__ unsigned short g_sil[2][B_][N_];
__device__ int            g_cel[2][B_][256];

// ================= FUSED LAUNCH 1: FPS level-1 (blocks 0-3) + lfp1 (4-19) ==
// FPS part: R13 form (bucketed, warp bbox prune, redundant redux merge,
// split float/ushort merge tuple). Exact vs jnp.argmax (skip = provable
// no-op; all reductions are max-value/min-ORIGINAL-index).
// lfp1 part (independent of FPS): lf = tanh(tanh(x W1+b1) W2+b2) and
// p1 = [lf, zone] @ c1W[:65] + c1b, re-tiled to 1024 threads = 16 groups
// of 64; ALIASES the FPS shared arrays (disjoint blocks, same launch).
__global__ __launch_bounds__(1024, 1) void fps1_lfp1_kernel(
    const float* __restrict__ x, const float* __restrict__ zones,
    const float* __restrict__ W1, const float* __restrict__ b1,
    const float* __restrict__ W2, const float* __restrict__ b2,
    const float* __restrict__ c1W, const float* __restrict__ c1b,
    float* __restrict__ lf_out) {
    const int T = 1024, P = 4, N = N_, M = M1_;
    const unsigned FULL = 0xFFFFFFFFu;
    int tid = threadIdx.x;

    __shared__ float2 sxy[N];               // 32 KB
    __shared__ float spx[N], spy[N];        // 32 KB
    __shared__ unsigned short ssidx[N];     // 8 KB
    __shared__ int counts[256], offs[256], cursor[256];
    __shared__ float          sVv[2][32];
    __shared__ unsigned short sVi[2][32];

    if (blockIdx.x >= B_) {
        // ---------------- lfp1 branch (aliases FPS smem) ----------------
        float* sW2 = spx;                   // 4096 floats
        float* sWc = (float*)sxy;           // 4160 floats (fits 8192)
        float* sW1 = spy;                   // 128 floats
        float* sb1 = spy + 128;
        float* sb2 = spy + 192;
        float* sbc = spy + 256;
        float* st1 = (float*)ssidx;         // 1024 floats
        float* slf = ((float*)ssidx) + 1024;// 1024 floats (8 KB total)
        int grp = tid >> 6;                 // 0..15
        int gt  = tid & 63;                 // 0..63
        for (int i = tid; i < 64 * 64; i += 1024) sW2[i] = W2[i];
        for (int i = tid; i < 65 * 64; i += 1024) sWc[i] = c1W[i];
        if (tid < 128) sW1[tid] = W1[tid];
        if (tid < 64) { sb1[tid] = b1[tid]; sb2[tid] = b2[tid]; sbc[tid] = c1b[tid]; }
        __syncthreads();
        int row0 = (blockIdx.x - B_) * 1024 + grp * 64;
        float* myt1 = st1 + grp * 64;
        float* mylf = slf + grp * 64;
        for (int r = 0; r < 64; r++) {
            int row = row0 + r;
            float x0 = x[row * 2], x1 = x[row * 2 + 1];
            float t1 = tanhf(x0 * sW1[gt] + x1 * sW1[64 + gt] + sb1[gt]);
            myt1[gt] = t1;
            __syncthreads();
            float acc = sb2[gt];
#pragma unroll
            for (int c = 0; c < 64; c++) acc = fmaf(myt1[c], sW2[c * 64 + gt], acc);
            float lf = tanhf(acc);
            lf_out[row * 64 + gt] = lf;
            mylf[gt] = lf;
            __syncthreads();
            float z = zones[row];
            float acc2 = fmaf(z, sWc[64 * 64 + gt], sbc[gt]);
#pragma unroll
            for (int c = 0; c < 64; c++) acc2 = fmaf(mylf[c], sWc[c * 64 + gt], acc2);
            g_p1[row * 64 + gt] = acc2;
            __syncthreads();
        }
        return;
    }

    // ---------------- FPS level-1 branch ----------------
    int b = blockIdx.x;
    int wid = tid >> 5, lane = tid & 31;
    const float2* p = (const float2*)(x + (size_t)b * N * 2);
    float* cout = g_ctr1 + (size_t)b * M * 2;

    float rx[P], ry[P];
    int cid[P];
#pragma unroll
    for (int k = 0; k < P; k++) {
        float2 v = p[tid + k * T];
        rx[k] = v.x; ry[k] = v.y;
        sxy[tid + k * T] = v;
    }
    if (tid < 256) counts[tid] = 0;
    if (tid < 64) { sVv[tid >> 5][tid & 31] = 0.0f; sVi[tid >> 5][tid & 31] = 0xFFFFu; }
    __syncthreads();
#pragma unroll
    for (int k = 0; k < P; k++) {
        int cx = (int)fminf(fmaxf((rx[k] - GRID_LO) * GRID_INV, 0.f), 15.f);
        int cy = (int)fminf(fmaxf((ry[k] - GRID_LO) * GRID_INV, 0.f), 15.f);
        cid[k] = cy * 16 + cx;
        atomicAdd(&counts[cid[k]], 1);
    }
    __syncthreads();
    if (tid < 256) offs[tid] = counts[tid];
    __syncthreads();
    for (int d = 1; d < 256; d <<= 1) {
        int v = 0;
        if (tid < 256 && tid >= d) v = offs[tid - d];
        __syncthreads();
        if (tid < 256 && tid >= d) offs[tid] += v;
        __syncthreads();
    }
    if (tid < 256) cursor[tid] = offs[tid] - counts[tid];
    __syncthreads();
#pragma unroll
    for (int k = 0; k < P; k++) {
        int pos = atomicAdd(&cursor[cid[k]], 1);
        spx[pos] = rx[k]; spy[pos] = ry[k];
        ssidx[pos] = (unsigned short)(tid + k * T);
    }
    __syncthreads();

    for (int i = tid; i < N; i += T) {
        g_sxl[0][b][i] = spx[i];
        g_syl[0][b][i] = spy[i];
        g_sil[0][b][i] = ssidx[i];
    }
    if (tid < 256) g_cel[0][b][tid] = offs[tid];

    float px[P], py[P], md[P];
    unsigned sidx[P];
    float bx0 = 1e30f, bx1 = -1e30f, by0 = 1e30f, by1 = -1e30f;
    int base = tid * P;
#pragma unroll
    for (int k = 0; k < P; k++) {
        px[k] = spx[base + k]; py[k] = spy[base + k];
        sidx[k] = (unsigned)ssidx[base + k];
        md[k] = 1e10f;
        bx0 = fminf(bx0, px[k]); bx1 = fmaxf(bx1, px[k]);
        by0 = fminf(by0, py[k]); by1 = fmaxf(by1, py[k]);
    }
#pragma unroll
    for (int o = 16; o > 0; o >>= 1) {
        bx0 = fminf(bx0, __shfl_xor_sync(FULL, bx0, o));
        bx1 = fmaxf(bx1, __shfl_xor_sync(FULL, bx1, o));
        by0 = fminf(by0, __shfl_xor_sync(FULL, by0, o));
        by1 = fmaxf(by1, __shfl_xor_sync(FULL, by1, o));
    }
    __syncthreads();

    float2 c0 = sxy[0];
    float lx = c0.x, ly = c0.y;
    if (tid == 0) { cout[0] = lx; cout[1] = ly; }

    float wvf = 1e10f;
    unsigned wi_ = 0u;

    for (int t = 1; t < M; t++) {
        float ex = fmaxf(fmaxf(bx0 - lx, lx - bx1), 0.f);
        float ey = fmaxf(fmaxf(by0 - ly, ly - by1), 0.f);
        float lb = fmaf(ex, ex, ey * ey);
        if (lb < wvf) {
            float tb = -1.f;
#pragma unroll
            for (int k = 0; k < P; k++) {
                float dx = px[k] - lx, dy = py[k] - ly;
                float d2 = fmaf(dx, dx, dy * dy);
                md[k] = fminf(md[k], d2);
                tb = fmaxf(tb, md[k]);
            }
            unsigned bi = 0xFFFFFFFFu;
#pragma unroll
            for (int k = 0; k < P; k++)
                if (md[k] == tb && sidx[k] < bi) bi = sidx[k];
            unsigned vb = __float_as_uint(tb);
            unsigned wm = __reduce_max_sync(FULL, vb);
            unsigned cand = (vb == wm) ? bi : 0xFFFFFFFFu;
            wi_ = __reduce_min_sync(FULL, cand);
            wvf = __uint_as_float(wm);
        }
        int buf = t & 1;
        if (lane == 0) {
            sVv[buf][wid] = wvf;
            sVi[buf][wid] = (unsigned short)wi_;
        }
        __syncthreads();
        float v2f = sVv[buf][lane];
        unsigned i2 = (unsigned)sVi[buf][lane];
        unsigned v2 = __float_as_uint(v2f);
        unsigned m2 = __reduce_max_sync(FULL, v2);
        unsigned c2 = (v2 == m2) ? i2 : 0xFFFFFFFFu;
        unsigned gi = __reduce_min_sync(FULL, c2);
        float2 w = sxy[gi];
        lx = w.x; ly = w.y;
        if (tid == 0) { cout[t * 2] = lx; cout[t * 2 + 1] = ly; }
    }
}

// ================= FUSED LAUNCH 2: FPS level-2 (blocks 0-3) + sa1 ==========
// FPS2: R13 form over ctr1 (N=2048, M=512, T=512, P=4).
// sa1 (blocks 4..4+B*M1): independent of FPS2 — needs only FPS1 exports,
// ctr1, and g_p1, all complete before this launch. 512-thread scan of the
// <=2x2 grid cells overlapping the r=0.5 disk, then 64-thread aggregate.
__global__ __launch_bounds__(512, 1) void fps2_sa1_kernel(const float* __restrict__ c1W) {
    const unsigned FULL = 0xFFFFFFFFu;
    int tid = threadIdx.x;

    __shared__ float2 sxy[M1_];
    __shared__ float spx[M1_], spy[M1_];
    __shared__ unsigned short ssidx[M1_];
    __shared__ int counts[256], offs[256], cursor[256];
    __shared__ float          sVv[2][32];
    __shared__ unsigned short sVi[2][32];
    __shared__ float sdx[MAXNBR], sdy[MAXNBR];
    __shared__ int   snb[MAXNBR];
    __shared__ int   scnt;

    if (blockIdx.x >= B_) {
        // ---------------- sa1 branch ----------------
        const int M = M1_, F = F1_;
        const float R = 0.5f, R2 = 0.25f;
        int idx = blockIdx.x - B_;
        int i = idx & (M1_ - 1);
        int b = idx >> 11;              // / M1_
        if (tid == 0) scnt = 0;
        __syncthreads();
        float cx = g_ctr1[(b * M + i) * 2], cy = g_ctr1[(b * M + i) * 2 + 1];
        int ix0 = max(0, (int)((cx - R - GRID_LO) * GRID_INV));
        int ix1 = min(15, (int)((cx + R - GRID_LO) * GRID_INV));
        int iy0 = max(0, (int)((cy - R - GRID_LO) * GRID_INV));
        int iy1 = min(15, (int)((cy + R - GRID_LO) * GRID_INV));
        for (int gy = iy0; gy <= iy1; gy++) {
            int c0 = gy * 16 + ix0, c1 = gy * 16 + ix1;
            int s = (c0 == 0) ? 0 : g_cel[0][b][c0 - 1];
            int e = g_cel[0][b][c1];
            for (int j = s + tid; j < e; j += 512) {
                float dx = g_sxl[0][b][j] - cx;
                float dy = g_syl[0][b][j] - cy;
                float d2 = fmaf(dx, dx, dy * dy);
                if (d2 <= R2) {
                    int s2 = atomicAdd(&scnt, 1);
                    if (s2 < MAXNBR) {
                        snb[s2] = (int)g_sil[0][b][j];
                        sdx[s2] = dx; sdy[s2] = dy;
                    }
                }
            }
        }
        __syncthreads();
        if (tid >= F) return;
        int cnt = min(scnt, MAXNBR);
        float wx = c1W[65 * 64 + tid];
        float wy = c1W[66 * 64 + tid];
        float mx = -1e9f;
        const float* pb = g_p1 + (size_t)b * N_ * F;
        int n = 0;
        for (; n + 4 <= cnt; n += 4) {
            float v0 = pb[snb[n] * F + tid];
            float v1 = pb[snb[n + 1] * F + tid];
            float v2 = pb[snb[n + 2] * F + tid];
            float v3 = pb[snb[n + 3] * F + tid];
            float m0 = fmaf(sdx[n], wx, fmaf(sdy[n], wy, v0));
            float m1 = fmaf(sdx[n + 1], wx, fmaf(sdy[n + 1], wy, v1));
            float m2 = fmaf(sdx[n + 2], wx, fmaf(sdy[n + 2], wy, v2));
            float m3 = fmaf(sdx[n + 3], wx, fmaf(sdy[n + 3], wy, v3));
            mx = fmaxf(mx, fmaxf(fmaxf(m0, m1), fmaxf(m2, m3)));
        }
        for (; n < cnt; n++) {
            float m = fmaf(sdx[n], wx, fmaf(sdy[n], wy, pb[snb[n] * F + tid]));
            mx = fmaxf(mx, m);
        }
        g_h1[((size_t)b * M + i) * F + tid] = mx;
        return;
    }

    // ---------------- FPS level-2 branch ----------------
    const int T = 512, P = 4, N = M1_, M = M2_;
    int b = blockIdx.x;
    int wid = tid >> 5, lane = tid & 31;
    const float2* p = (const float2*)(g_ctr1 + (size_t)b * N * 2);
    float* cout = g_ctr2 + (size_t)b * M * 2;

    float rx[P], ry[P];
    int cid[P];
#pragma unroll
    for (int k = 0; k < P; k++) {
        float2 v = p[tid + k * T];
        rx[k] = v.x; ry[k] = v.y;
        sxy[tid + k * T] = v;
    }
    if (tid < 256) counts[tid] = 0;
    if (tid < 64) { sVv[tid >> 5][tid & 31] = 0.0f; sVi[tid >> 5][tid & 31] = 0xFFFFu; }
    __syncthreads();
#pragma unroll
    for (int k = 0; k < P; k++) {
        int cx = (int)fminf(fmaxf((rx[k] - GRID_LO) * GRID_INV, 0.f), 15.f);
        int cy = (int)fminf(fmaxf((ry[k] - GRID_LO) * GRID_INV, 0.f), 15.f);
        cid[k] = cy * 16 + cx;
        atomicAdd(&counts[cid[k]], 1);
    }
    __syncthreads();
    if (tid < 256) offs[tid] = counts[tid];
    __syncthreads();
    for (int d = 1; d < 256; d <<= 1) {
        int v = 0;
        if (tid < 256 && tid >= d) v = offs[tid - d];
        __syncthreads();
        if (tid < 256 && tid >= d) offs[tid] += v;
        __syncthreads();
    }
    if (tid < 256) cursor[tid] = offs[tid] - counts[tid];
    __syncthreads();
#pragma unroll
    for (int k = 0; k < P; k++) {
        int pos = atomicAdd(&cursor[cid[k]], 1);
        spx[pos] = rx[k]; spy[pos] = ry[k];
        ssidx[pos] = (unsigned short)(tid + k * T);
    }
    __syncthreads();

    for (int i = tid; i < N; i += T) {
        g_sxl[1][b][i] = spx[i];
        g_syl[1][b][i] = spy[i];
        g_sil[1][b][i] = ssidx[i];
    }
    if (tid < 256) g_cel[1][b][tid] = offs[tid];

    float px[P], py[P], md[P];
    unsigned sidx[P];
    float bx0 = 1e30f, bx1 = -1e30f, by0 = 1e30f, by1 = -1e30f;
    int base = tid * P;
#pragma unroll
    for (int k = 0; k < P; k++) {
        px[k] = spx[base + k]; py[k] = spy[base + k];
        sidx[k] = (unsigned)ssidx[base + k];
        md[k] = 1e10f;
        bx0 = fminf(bx0, px[k]); bx1 = fmaxf(bx1, px[k]);
        by0 = fminf(by0, py[k]); by1 = fmaxf(by1, py[k]);
    }
#pragma unroll
    for (int o = 16; o > 0; o >>= 1) {
        bx0 = fminf(bx0, __shfl_xor_sync(FULL, bx0, o));
        bx1 = fmaxf(bx1, __shfl_xor_sync(FULL, bx1, o));
        by0 = fminf(by0, __shfl_xor_sync(FULL, by0, o));
        by1 = fmaxf(by1, __shfl_xor_sync(FULL, by1, o));
    }
    __syncthreads();

    float2 c0 = sxy[0];
    float lx = c0.x, ly = c0.y;
    if (tid == 0) { cout[0] = lx; cout[1] = ly; }

    float wvf = 1e10f;
    unsigned wi_ = 0u;

    for (int t = 1; t < M; t++) {
        float ex = fmaxf(fmaxf(bx0 - lx, lx - bx1), 0.f);
        float ey = fmaxf(fmaxf(by0 - ly, ly - by1), 0.f);
        float lb = fmaf(ex, ex, ey * ey);
        if (lb < wvf) {
            float tb = -1.f;
#pragma unroll
            for (int k = 0; k < P; k++) {
                float dx = px[k] - lx, dy = py[k] - ly;
                float d2 = fmaf(dx, dx, dy * dy);
                md[k] = fminf(md[k], d2);
                tb = fmaxf(tb, md[k]);
            }
            unsigned bi = 0xFFFFFFFFu;
#pragma unroll
            for (int k = 0; k < P; k++)
                if (md[k] == tb && sidx[k] < bi) bi = sidx[k];
            unsigned vb = __float_as_uint(tb);
            unsigned wm = __reduce_max_sync(FULL, vb);
            unsigned cand = (vb == wm) ? bi : 0xFFFFFFFFu;
            wi_ = __reduce_min_sync(FULL, cand);
            wvf = __uint_as_float(wm);
        }
        int buf = t & 1;
        if (lane == 0) {
            sVv[buf][wid] = wvf;
            sVi[buf][wid] = (unsigned short)wi_;
        }
        __syncthreads();
        float v2f = sVv[buf][lane];
        unsigned i2 = (unsigned)sVi[buf][lane];
        unsigned v2 = __float_as_uint(v2f);
        unsigned m2 = __reduce_max_sync(FULL, v2);
        unsigned c2 = (v2 == m2) ? i2 : 0xFFFFFFFFu;
        unsigned gi = __reduce_min_sync(FULL, c2);
        float2 w = sxy[gi];
        lx = w.x; ly = w.y;
        if (tid == 0) { cout[t * 2] = lx; cout[t * 2 + 1] = ly; }
    }
}

// ---------------- p2[j] = h1_j @ c2W[:64] + c2b ---------------------------
__global__ void p2_kernel(const float* __restrict__ c2W, const float* __restrict__ c2b) {
    __shared__ float sW[64 * 128];
    __shared__ float sb[128];
    __shared__ float srow[64];
    int tid = threadIdx.x;  // 128
    for (int i = tid; i < 64 * 128; i += 128) sW[i] = c2W[i];
    sb[tid] = c2b[tid];
    __syncthreads();
    int row0 = blockIdx.x * 32;
    for (int r = 0; r < 32; r++) {
        int row = row0 + r;
        if (tid < 64) srow[tid] = g_h1[row * 64 + tid];
        __syncthreads();
        float acc = sb[tid];
#pragma unroll
        for (int c = 0; c < 64; c++) acc = fmaf(srow[c], sW[c * 128 + tid], acc);
        g_p2[row * 128 + tid] = acc;
        __syncthreads();
    }
}

// ---------------- SA2: grid-pruned (r=1.0 over ctr1 via FPS2's sort) ------
__global__ void sa2_kernel(const float* __restrict__ c2W) {
    const int M = M2_, F = F2_;
    const float R = 1.0f, R2 = 1.0f;
    int i = blockIdx.x, b = blockIdx.y, tid = threadIdx.x;  // 128
    __shared__ float sdx[MAXNBR], sdy[MAXNBR];
    __shared__ int   snb[MAXNBR];
    __shared__ int   scnt;
    if (tid == 0) scnt = 0;
    __syncthreads();
    float cx = g_ctr2[(b * M + i) * 2], cy = g_ctr2[(b * M + i) * 2 + 1];
    int ix0 = max(0, (int)((cx - R - GRID_LO) * GRID_INV));
    int ix1 = min(15, (int)((cx + R - GRID_LO) * GRID_INV));
    int iy0 = max(0, (int)((cy - R - GRID_LO) * GRID_INV));
    int iy1 = min(15, (int)((cy + R - GRID_LO) * GRID_INV));
    for (int gy = iy0; gy <= iy1; gy++) {
        int c0 = gy * 16 + ix0, c1 = gy * 16 + ix1;
        int s = (c0 == 0) ? 0 : g_cel[1][b][c0 - 1];
        int e = g_cel[1][b][c1];
        for (int j = s + tid; j < e; j += F) {
            float dx = g_sxl[1][b][j] - cx;
            float dy = g_syl[1][b][j] - cy;
            float d2 = fmaf(dx, dx, dy * dy);
            if (d2 <= R2) {
                int s2 = atomicAdd(&scnt, 1);
                if (s2 < MAXNBR) {
                    snb[s2] = (int)g_sil[1][b][j];
                    sdx[s2] = dx; sdy[s2] = dy;
                }
            }
        }
    }
    __syncthreads();
    int cnt = min(scnt, MAXNBR);
    float wx = c2W[64 * 128 + tid];
    float wy = c2W[65 * 128 + tid];
    float mx = -1e9f;
    const float* pb = g_p2 + (size_t)b * M1_ * F;
    int n = 0;
    for (; n + 4 <= cnt; n += 4) {
        float v0 = pb[snb[n] * F + tid];
        float v1 = pb[snb[n + 1] * F + tid];
        float v2 = pb[snb[n + 2] * F + tid];
        float v3 = pb[snb[n + 3] * F + tid];
        float m0 = fmaf(sdx[n], wx, fmaf(sdy[n], wy, v0));
        float m1 = fmaf(sdx[n + 1], wx, fmaf(sdy[n + 1], wy, v1));
        float m2 = fmaf(sdx[n + 2], wx, fmaf(sdy[n + 2], wy, v2));
        float m3 = fmaf(sdx[n + 3], wx, fmaf(sdy[n + 3], wy, v3));
        mx = fmaxf(mx, fmaxf(fmaxf(m0, m1), fmaxf(m2, m3)));
    }
    for (; n < cnt; n++) {
        float m = fmaf(sdx[n], wx, fmaf(sdy[n], wy, pb[snb[n] * F + tid]));
        mx = fmaxf(mx, m);
    }
    g_h2[((size_t)b * M + i) * F + tid] = mx;
}

// ---------------- final projection + partial max pool ---------------------
__global__ void final_partial(const float* __restrict__ W, const float* __restrict__ bias) {
    int fchunk = blockIdx.x, rchunk = blockIdx.y, b = blockIdx.z;
    int tid = threadIdx.x;  // 128
    int f = fchunk * 128 + tid;
    __shared__ float sh[64][132];
    int r0 = rchunk * 64;
    for (int e = tid; e < 64 * 130; e += 128) {
        int r = e / 130, c = e % 130;
        float v;
        if (c < 128) v = g_h2[((size_t)b * M2_ + r0 + r) * 128 + c];
        else         v = g_ctr2[(b * M2_ + r0 + r) * 2 + (c - 128)];
        sh[r][c] = v;
    }
    __syncthreads();
    float acc[64];
#pragma unroll
    for (int r = 0; r < 64; r++) acc[r] = 0.0f;
    for (int c = 0; c < 130; c++) {
        float w = W[c * 1024 + f];
#pragma unroll
        for (int r = 0; r < 64; r++) acc[r] = fmaf(sh[r][c], w, acc[r]);
    }
    float mx = acc[0];
#pragma unroll
    for (int r = 1; r < 64; r++) mx = fmaxf(mx, acc[r]);
    g_pmax[(b * 8 + rchunk) * 1024 + f] = mx + bias[f];
}

__global__ void final_reduce(float* __restrict__ gf) {
    int b = blockIdx.x, f = threadIdx.x;  // 1024
    float mx = g_pmax[(b * 8) * 1024 + f];
#pragma unroll
    for (int r = 1; r < 8; r++) mx = fmaxf(mx, g_pmax[(b * 8 + r) * 1024 + f]);
    gf[b * 1024 + f] = mx;
}

// ---------------- launch ---------------------------------------------------
extern "C" void kernel_launch(void* const* d_in, const int* in_sizes, int n_in,
                              void* d_out, int out_size) {
    const float* x     = (const float*)d_in[0];
    const float* zones = (const float*)d_in[1];
    const float* lf_W1 = (const float*)d_in[2];
    const float* lf_b1 = (const float*)d_in[3];
    const float* lf_W2 = (const float*)d_in[4];
    const float* lf_b2 = (const float*)d_in[5];
    const float* c1_W  = (const float*)d_in[6];
    const float* c1_b  = (const float*)d_in[7];
    const float* c2_W  = (const float*)d_in[8];
    const float* c2_b  = (const float*)d_in[9];
    const float* c3_W  = (const float*)d_in[10];
    const float* c3_b  = (const float*)d_in[11];

    float* lf_out = (float*)d_out;
    float* gf_out = (float*)d_out + (size_t)B_ * N_ * LF_;

    // Launch 1: FPS level-1 (4 blocks) + lfp1 (16 blocks) — independent work
    fps1_lfp1_kernel<<<B_ + 16, 1024>>>(x, zones, lf_W1, lf_b1, lf_W2, lf_b2,
                                        c1_W, c1_b, lf_out);
    // Launch 2: FPS level-2 (4 blocks) + sa1 (B*M1 blocks) — sa1 independent of FPS2
    fps2_sa1_kernel<<<B_ + B_ * M1_, 512>>>(c1_W);
    p2_kernel<<<(B_ * M1_) / 32, 128>>>(c2_W, c2_b);
    sa2_kernel<<<dim3(M2_, B_), F2_>>>(c2_W);
    final_partial<<<dim3(8, 8, B_), 128>>>(c3_W, c3_b);
    final_reduce<<<B_, 1024>>>(gf_out);
}

// round 16
// speedup vs baseline: 1.3960x; 1.0211x over previous
#include <cuda_runtime.h>
#include <cuda_bf16.h>
#include <cstdint>

#define B_  4
#define N_  4096
#define M1_ 2048
#define M2_ 512
#define F1_ 64
#define F2_ 128
#define F3_ 1024
#define LF_ 64
#define MAXNBR 128

#define GRID_LO   (-18.0f)
#define GRID_INV  (16.0f / 36.0f)

// ---------------- device scratch ----------------
__device__ float g_p1  [B_ * N_  * F1_];
__device__ float g_ctr1[B_ * M1_ * 2];
__device__ float g_p2  [B_ * M1_ * F2_];
__device__ float g_h2  [B_ * M2_ * F2_];
__device__ float g_ctr2[B_ * M2_ * 2];
__device__ float g_pmax[B_ * 8 * F3_];
// exported bucket sort (level 0: x points, level 1: ctr1 points)
__device__ float2         g_sxy2[2][B_][N_];
__device__ unsigned short g_sil[2][B_][N_];
__device__ int            g_cel[2][B_][256];

// ================= FUSED LAUNCH 1: FPS level-1 (blocks 0-3) + lfp1 (4-19) ==
__global__ __launch_bounds__(1024, 1) void fps1_lfp1_kernel(
    const float* __restrict__ x, const float* __restrict__ zones,
    const float* __restrict__ W1, const float* __restrict__ b1,
    const float* __restrict__ W2, const float* __restrict__ b2,
    const float* __restrict__ c1W, const float* __restrict__ c1b,
    float* __restrict__ lf_out) {
    const int T = 1024, P = 4, N = N_, M = M1_;
    const unsigned FULL = 0xFFFFFFFFu;
    int tid = threadIdx.x;

    __shared__ float2 sxy[N];
    __shared__ float spx[N], spy[N];
    __shared__ unsigned short ssidx[N];
    __shared__ int counts[256], offs[256], cursor[256];
    __shared__ float          sVv[2][32];
    __shared__ unsigned short sVi[2][32];

    if (blockIdx.x >= B_) {
        // ---------------- lfp1 branch (aliases FPS smem) ----------------
        float* sW2 = spx;
        float* sWc = (float*)sxy;
        float* sW1 = spy;
        float* sb1 = spy + 128;
        float* sb2 = spy + 192;
        float* sbc = spy + 256;
        float* st1 = (float*)ssidx;
        float* slf = ((float*)ssidx) + 1024;
        int grp = tid >> 6;
        int gt  = tid & 63;
        for (int i = tid; i < 64 * 64; i += 1024) sW2[i] = W2[i];
        for (int i = tid; i < 65 * 64; i += 1024) sWc[i] = c1W[i];
        if (tid < 128) sW1[tid] = W1[tid];
        if (tid < 64) { sb1[tid] = b1[tid]; sb2[tid] = b2[tid]; sbc[tid] = c1b[tid]; }
        __syncthreads();
        int row0 = (blockIdx.x - B_) * 1024 + grp * 64;
        float* myt1 = st1 + grp * 64;
        float* mylf = slf + grp * 64;
        for (int r = 0; r < 64; r++) {
            int row = row0 + r;
            float x0 = x[row * 2], x1 = x[row * 2 + 1];
            float t1 = tanhf(x0 * sW1[gt] + x1 * sW1[64 + gt] + sb1[gt]);
            myt1[gt] = t1;
            __syncthreads();
            float acc = sb2[gt];
#pragma unroll
            for (int c = 0; c < 64; c++) acc = fmaf(myt1[c], sW2[c * 64 + gt], acc);
            float lf = tanhf(acc);
            lf_out[row * 64 + gt] = lf;
            mylf[gt] = lf;
            __syncthreads();
            float z = zones[row];
            float acc2 = fmaf(z, sWc[64 * 64 + gt], sbc[gt]);
#pragma unroll
            for (int c = 0; c < 64; c++) acc2 = fmaf(mylf[c], sWc[c * 64 + gt], acc2);
            g_p1[row * 64 + gt] = acc2;
            __syncthreads();
        }
        return;
    }

    // ---------------- FPS level-1 branch (R13 form) ----------------
    int b = blockIdx.x;
    int wid = tid >> 5, lane = tid & 31;
    const float2* p = (const float2*)(x + (size_t)b * N * 2);
    float* cout = g_ctr1 + (size_t)b * M * 2;

    float rx[P], ry[P];
    int cid[P];
#pragma unroll
    for (int k = 0; k < P; k++) {
        float2 v = p[tid + k * T];
        rx[k] = v.x; ry[k] = v.y;
        sxy[tid + k * T] = v;
    }
    if (tid < 256) counts[tid] = 0;
    if (tid < 64) { sVv[tid >> 5][tid & 31] = 0.0f; sVi[tid >> 5][tid & 31] = 0xFFFFu; }
    __syncthreads();
#pragma unroll
    for (int k = 0; k < P; k++) {
        int cx = (int)fminf(fmaxf((rx[k] - GRID_LO) * GRID_INV, 0.f), 15.f);
        int cy = (int)fminf(fmaxf((ry[k] - GRID_LO) * GRID_INV, 0.f), 15.f);
        cid[k] = cy * 16 + cx;
        atomicAdd(&counts[cid[k]], 1);
    }
    __syncthreads();
    if (tid < 256) offs[tid] = counts[tid];
    __syncthreads();
    for (int d = 1; d < 256; d <<= 1) {
        int v = 0;
        if (tid < 256 && tid >= d) v = offs[tid - d];
        __syncthreads();
        if (tid < 256 && tid >= d) offs[tid] += v;
        __syncthreads();
    }
    if (tid < 256) cursor[tid] = offs[tid] - counts[tid];
    __syncthreads();
#pragma unroll
    for (int k = 0; k < P; k++) {
        int pos = atomicAdd(&cursor[cid[k]], 1);
        spx[pos] = rx[k]; spy[pos] = ry[k];
        ssidx[pos] = (unsigned short)(tid + k * T);
    }
    __syncthreads();

    for (int i = tid; i < N; i += T) {
        g_sxy2[0][b][i] = make_float2(spx[i], spy[i]);
        g_sil[0][b][i] = ssidx[i];
    }
    if (tid < 256) g_cel[0][b][tid] = offs[tid];

    float px[P], py[P], md[P];
    unsigned sidx[P];
    float bx0 = 1e30f, bx1 = -1e30f, by0 = 1e30f, by1 = -1e30f;
    int base = tid * P;
#pragma unroll
    for (int k = 0; k < P; k++) {
        px[k] = spx[base + k]; py[k] = spy[base + k];
        sidx[k] = (unsigned)ssidx[base + k];
        md[k] = 1e10f;
        bx0 = fminf(bx0, px[k]); bx1 = fmaxf(bx1, px[k]);
        by0 = fminf(by0, py[k]); by1 = fmaxf(by1, py[k]);
    }
#pragma unroll
    for (int o = 16; o > 0; o >>= 1) {
        bx0 = fminf(bx0, __shfl_xor_sync(FULL, bx0, o));
        bx1 = fmaxf(bx1, __shfl_xor_sync(FULL, bx1, o));
        by0 = fminf(by0, __shfl_xor_sync(FULL, by0, o));
        by1 = fmaxf(by1, __shfl_xor_sync(FULL, by1, o));
    }
    __syncthreads();

    float2 c0 = sxy[0];
    float lx = c0.x, ly = c0.y;
    if (tid == 0) { cout[0] = lx; cout[1] = ly; }

    float wvf = 1e10f;
    unsigned wi_ = 0u;

    for (int t = 1; t < M; t++) {
        float ex = fmaxf(fmaxf(bx0 - lx, lx - bx1), 0.f);
        float ey = fmaxf(fmaxf(by0 - ly, ly - by1), 0.f);
        float lb = fmaf(ex, ex, ey * ey);
        if (lb < wvf) {
            float tb = -1.f;
#pragma unroll
            for (int k = 0; k < P; k++) {
                float dx = px[k] - lx, dy = py[k] - ly;
                float d2 = fmaf(dx, dx, dy * dy);
                md[k] = fminf(md[k], d2);
                tb = fmaxf(tb, md[k]);
            }
            unsigned bi = 0xFFFFFFFFu;
#pragma unroll
            for (int k = 0; k < P; k++)
                if (md[k] == tb && sidx[k] < bi) bi = sidx[k];
            unsigned vb = __float_as_uint(tb);
            unsigned wm = __reduce_max_sync(FULL, vb);
            unsigned cand = (vb == wm) ? bi : 0xFFFFFFFFu;
            wi_ = __reduce_min_sync(FULL, cand);
            wvf = __uint_as_float(wm);
        }
        int buf = t & 1;
        if (lane == 0) {
            sVv[buf][wid] = wvf;
            sVi[buf][wid] = (unsigned short)wi_;
        }
        __syncthreads();
        float v2f = sVv[buf][lane];
        unsigned i2 = (unsigned)sVi[buf][lane];
        unsigned v2 = __float_as_uint(v2f);
        unsigned m2 = __reduce_max_sync(FULL, v2);
        unsigned c2 = (v2 == m2) ? i2 : 0xFFFFFFFFu;
        unsigned gi = __reduce_min_sync(FULL, c2);
        float2 w = sxy[gi];
        lx = w.x; ly = w.y;
        if (tid == 0) { cout[t * 2] = lx; cout[t * 2 + 1] = ly; }
    }
}

// ===== FUSED LAUNCH 2: FPS level-2 (blocks 0-3) + sa1+p2 (4..4+B*M1) ======
// sa1+p2 branch: computes h1 row (64 features) for its center in registers,
// stages it in smem, then computes p2[row] = h1row @ c2W[:64] + c2b with
// c2W staged in aliased smem. Eliminates standalone p2 kernel and g_h1.
__global__ __launch_bounds__(512, 1) void fps2_sa1_kernel(
    const float* __restrict__ c1W,
    const float* __restrict__ c2W, const float* __restrict__ c2b) {
    const unsigned FULL = 0xFFFFFFFFu;
    int tid = threadIdx.x;

    __shared__ __align__(16) unsigned char sraw[40320];

    if (blockIdx.x >= B_) {
        // ---------------- sa1 + p2 branch ----------------
        float* sW   = (float*)sraw;                   // 8192 floats (32 KB)
        float* sb   = (float*)(sraw + 32768);         // 128
        float* h1s  = (float*)(sraw + 33280);         // 64
        float* sdx  = (float*)(sraw + 33536);         // 128
        float* sdy  = (float*)(sraw + 34048);         // 128
        int*   snb  = (int*)(sraw + 34560);           // 128
        int*   scnt = (int*)(sraw + 35072);

        const int M = M1_, F = F1_;
        const float R = 0.5f, R2 = 0.25f;
        int idx = blockIdx.x - B_;
        int i = idx & (M1_ - 1);
        int b = idx >> 11;
        for (int k = tid; k < 64 * 128; k += 512) sW[k] = c2W[k];
        if (tid < 128) sb[tid] = c2b[tid];
        if (tid == 0) *scnt = 0;
        __syncthreads();
        float cx = g_ctr1[(b * M + i) * 2], cy = g_ctr1[(b * M + i) * 2 + 1];
        int ix0 = max(0, (int)((cx - R - GRID_LO) * GRID_INV));
        int ix1 = min(15, (int)((cx + R - GRID_LO) * GRID_INV));
        int iy0 = max(0, (int)((cy - R - GRID_LO) * GRID_INV));
        int iy1 = min(15, (int)((cy + R - GRID_LO) * GRID_INV));
        for (int gy = iy0; gy <= iy1; gy++) {
            int c0 = gy * 16 + ix0, c1 = gy * 16 + ix1;
            int s = (c0 == 0) ? 0 : g_cel[0][b][c0 - 1];
            int e = g_cel[0][b][c1];
            for (int j = s + tid; j < e; j += 512) {
                float2 pj = g_sxy2[0][b][j];
                float dx = pj.x - cx, dy = pj.y - cy;
                float d2 = fmaf(dx, dx, dy * dy);
                if (d2 <= R2) {
                    int s2 = atomicAdd(scnt, 1);
                    if (s2 < MAXNBR) {
                        snb[s2] = (int)g_sil[0][b][j];
                        sdx[s2] = dx; sdy[s2] = dy;
                    }
                }
            }
        }
        __syncthreads();
        int cnt = min(*scnt, MAXNBR);
        if (tid < F) {
            float wx = c1W[65 * 64 + tid];
            float wy = c1W[66 * 64 + tid];
            float mx = -1e9f;
            const float* pb = g_p1 + (size_t)b * N_ * F;
            int n = 0;
            for (; n + 4 <= cnt; n += 4) {
                float v0 = pb[snb[n] * F + tid];
                float v1 = pb[snb[n + 1] * F + tid];
                float v2 = pb[snb[n + 2] * F + tid];
                float v3 = pb[snb[n + 3] * F + tid];
                float m0 = fmaf(sdx[n], wx, fmaf(sdy[n], wy, v0));
                float m1 = fmaf(sdx[n + 1], wx, fmaf(sdy[n + 1], wy, v1));
                float m2 = fmaf(sdx[n + 2], wx, fmaf(sdy[n + 2], wy, v2));
                float m3 = fmaf(sdx[n + 3], wx, fmaf(sdy[n + 3], wy, v3));
                mx = fmaxf(mx, fmaxf(fmaxf(m0, m1), fmaxf(m2, m3)));
            }
            for (; n < cnt; n++) {
                float m = fmaf(sdx[n], wx, fmaf(sdy[n], wy, pb[snb[n] * F + tid]));
                mx = fmaxf(mx, m);
            }
            h1s[tid] = mx;
        }
        __syncthreads();
        if (tid < 128) {
            float acc = sb[tid];
#pragma unroll
            for (int c = 0; c < 64; c++) acc = fmaf(h1s[c], sW[c * 128 + tid], acc);
            g_p2[((size_t)b * M + i) * 128 + tid] = acc;
        }
        return;
    }

    // ---------------- FPS level-2 branch (R13 form) ----------------
    const int T = 512, P = 4, N = M1_, M = M2_;
    float2* sxy = (float2*)sraw;                          // 2048 (16 KB)
    float*  spx = (float*)(sraw + 16384);                 // 2048
    float*  spy = (float*)(sraw + 24576);                 // 2048
    unsigned short* ssidx = (unsigned short*)(sraw + 32768);  // 2048 (4 KB)
    int* counts = (int*)(sraw + 36864);                   // 256
    int* offs   = (int*)(sraw + 37888);                   // 256
    // reuse counts area for cursor after scan? keep separate within budget:
    float*          sVv = (float*)(sraw + 38912);         // 64 floats (256 B)
    unsigned short* sVi = (unsigned short*)(sraw + 39168);// 64 (128 B)
    int* cursor = (int*)(sraw + 39296);                   // 256 ints -> 1024 B (ends 40320)

    int b = blockIdx.x;
    int wid = tid >> 5, lane = tid & 31;
    const float2* p = (const float2*)(g_ctr1 + (size_t)b * N * 2);
    float* cout = g_ctr2 + (size_t)b * M * 2;

    float rx[P], ry[P];
    int cid[P];
#pragma unroll
    for (int k = 0; k < P; k++) {
        float2 v = p[tid + k * T];
        rx[k] = v.x; ry[k] = v.y;
        sxy[tid + k * T] = v;
    }
    if (tid < 256) counts[tid] = 0;
    if (tid < 64) { sVv[tid] = 0.0f; sVi[tid] = 0xFFFFu; }
    __syncthreads();
#pragma unroll
    for (int k = 0; k < P; k++) {
        int cx = (int)fminf(fmaxf((rx[k] - GRID_LO) * GRID_INV, 0.f), 15.f);
        int cy = (int)fminf(fmaxf((ry[k] - GRID_LO) * GRID_INV, 0.f), 15.f);
        cid[k] = cy * 16 + cx;
        atomicAdd(&counts[cid[k]], 1);
    }
    __syncthreads();
    if (tid < 256) offs[tid] = counts[tid];
    __syncthreads();
    for (int d = 1; d < 256; d <<= 1) {
        int v = 0;
        if (tid < 256 && tid >= d) v = offs[tid - d];
        __syncthreads();
        if (tid < 256 && tid >= d) offs[tid] += v;
        __syncthreads();
    }
    if (tid < 256) cursor[tid] = offs[tid] - counts[tid];
    __syncthreads();
#pragma unroll
    for (int k = 0; k < P; k++) {
        int pos = atomicAdd(&cursor[cid[k]], 1);
        spx[pos] = rx[k]; spy[pos] = ry[k];
        ssidx[pos] = (unsigned short)(tid + k * T);
    }
    __syncthreads();

    for (int i = tid; i < N; i += T) {
        g_sxy2[1][b][i] = make_float2(spx[i], spy[i]);
        g_sil[1][b][i] = ssidx[i];
    }
    if (tid < 256) g_cel[1][b][tid] = offs[tid];

    float px[P], py[P], md[P];
    unsigned sidx[P];
    float bx0 = 1e30f, bx1 = -1e30f, by0 = 1e30f, by1 = -1e30f;
    int base = tid * P;
#pragma unroll
    for (int k = 0; k < P; k++) {
        px[k] = spx[base + k]; py[k] = spy[base + k];
        sidx[k] = (unsigned)ssidx[base + k];
        md[k] = 1e10f;
        bx0 = fminf(bx0, px[k]); bx1 = fmaxf(bx1, px[k]);
        by0 = fminf(by0, py[k]); by1 = fmaxf(by1, py[k]);
    }
#pragma unroll
    for (int o = 16; o > 0; o >>= 1) {
        bx0 = fminf(bx0, __shfl_xor_sync(FULL, bx0, o));
        bx1 = fmaxf(bx1, __shfl_xor_sync(FULL, bx1, o));
        by0 = fminf(by0, __shfl_xor_sync(FULL, by0, o));
        by1 = fmaxf(by1, __shfl_xor_sync(FULL, by1, o));
    }
    __syncthreads();

    float2 c0 = sxy[0];
    float lx = c0.x, ly = c0.y;
    if (tid == 0) { cout[0] = lx; cout[1] = ly; }

    float wvf = 1e10f;
    unsigned wi_ = 0u;

    for (int t = 1; t < M; t++) {
        float ex = fmaxf(fmaxf(bx0 - lx, lx - bx1), 0.f);
        float ey = fmaxf(fmaxf(by0 - ly, ly - by1), 0.f);
        float lb = fmaf(ex, ex, ey * ey);
        if (lb < wvf) {
            float tb = -1.f;
#pragma unroll
            for (int k = 0; k < P; k++) {
                float dx = px[k] - lx, dy = py[k] - ly;
                float d2 = fmaf(dx, dx, dy * dy);
                md[k] = fminf(md[k], d2);
                tb = fmaxf(tb, md[k]);
            }
            unsigned bi = 0xFFFFFFFFu;
#pragma unroll
            for (int k = 0; k < P; k++)
                if (md[k] == tb && sidx[k] < bi) bi = sidx[k];
            unsigned vb = __float_as_uint(tb);
            unsigned wm = __reduce_max_sync(FULL, vb);
            unsigned cand = (vb == wm) ? bi : 0xFFFFFFFFu;
            wi_ = __reduce_min_sync(FULL, cand);
            wvf = __uint_as_float(wm);
        }
        int buf = t & 1;
        if (lane == 0) {
            sVv[buf * 32 + wid] = wvf;
            sVi[buf * 32 + wid] = (unsigned short)wi_;
        }
        __syncthreads();
        float v2f = sVv[buf * 32 + lane];
        unsigned i2 = (unsigned)sVi[buf * 32 + lane];
        unsigned v2 = __float_as_uint(v2f);
        unsigned m2 = __reduce_max_sync(FULL, v2);
        unsigned c2 = (v2 == m2) ? i2 : 0xFFFFFFFFu;
        unsigned gi = __reduce_min_sync(FULL, c2);
        float2 w = sxy[gi];
        lx = w.x; ly = w.y;
        if (tid == 0) { cout[t * 2] = lx; cout[t * 2 + 1] = ly; }
    }
}

// ---------------- SA2: grid-pruned (r=1.0 over ctr1 via FPS2's sort) ------
__global__ void sa2_kernel(const float* __restrict__ c2W) {
    const int M = M2_, F = F2_;
    const float R = 1.0f, R2 = 1.0f;
    int i = blockIdx.x, b = blockIdx.y, tid = threadIdx.x;  // 128
    __shared__ float sdx[MAXNBR], sdy[MAXNBR];
    __shared__ int   snb[MAXNBR];
    __shared__ int   scnt;
    if (tid == 0) scnt = 0;
    __syncthreads();
    float cx = g_ctr2[(b * M + i) * 2], cy = g_ctr2[(b * M + i) * 2 + 1];
    int ix0 = max(0, (int)((cx - R - GRID_LO) * GRID_INV));
    int ix1 = min(15, (int)((cx + R - GRID_LO) * GRID_INV));
    int iy0 = max(0, (int)((cy - R - GRID_LO) * GRID_INV));
    int iy1 = min(15, (int)((cy + R - GRID_LO) * GRID_INV));
    for (int gy = iy0; gy <= iy1; gy++) {
        int c0 = gy * 16 + ix0, c1 = gy * 16 + ix1;
        int s = (c0 == 0) ? 0 : g_cel[1][b][c0 - 1];
        int e = g_cel[1][b][c1];
        for (int j = s + tid; j < e; j += F) {
            float2 pj = g_sxy2[1][b][j];
            float dx = pj.x - cx, dy = pj.y - cy;
            float d2 = fmaf(dx, dx, dy * dy);
            if (d2 <= R2) {
                int s2 = atomicAdd(&scnt, 1);
                if (s2 < MAXNBR) {
                    snb[s2] = (int)g_sil[1][b][j];
                    sdx[s2] = dx; sdy[s2] = dy;
                }
            }
        }
    }
    __syncthreads();
    int cnt = min(scnt, MAXNBR);
    float wx = c2W[64 * 128 + tid];
    float wy = c2W[65 * 128 + tid];
    float mx = -1e9f;
    const float* pb = g_p2 + (size_t)b * M1_ * F;
    int n = 0;
    for (; n + 4 <= cnt; n += 4) {
        float v0 = pb[snb[n] * F + tid];
        float v1 = pb[snb[n + 1] * F + tid];
        float v2 = pb[snb[n + 2] * F + tid];
        float v3 = pb[snb[n + 3] * F + tid];
        float m0 = fmaf(sdx[n], wx, fmaf(sdy[n], wy, v0));
        float m1 = fmaf(sdx[n + 1], wx, fmaf(sdy[n + 1], wy, v1));
        float m2 = fmaf(sdx[n + 2], wx, fmaf(sdy[n + 2], wy, v2));
        float m3 = fmaf(sdx[n + 3], wx, fmaf(sdy[n + 3], wy, v3));
        mx = fmaxf(mx, fmaxf(fmaxf(m0, m1), fmaxf(m2, m3)));
    }
    for (; n < cnt; n++) {
        float m = fmaf(sdx[n], wx, fmaf(sdy[n], wy, pb[snb[n] * F + tid]));
        mx = fmaxf(mx, m);
    }
    g_h2[((size_t)b * M + i) * F + tid] = mx;
}

// ---------------- final projection + partial max pool ---------------------
__global__ void final_partial(const float* __restrict__ W, const float* __restrict__ bias) {
    int fchunk = blockIdx.x, rchunk = blockIdx.y, b = blockIdx.z;
    int tid = threadIdx.x;  // 128
    int f = fchunk * 128 + tid;
    __shared__ float sh[64][132];
    int r0 = rchunk * 64;
    for (int e = tid; e < 64 * 130; e += 128) {
        int r = e / 130, c = e % 130;
        float v;
        if (c < 128) v = g_h2[((size_t)b * M2_ + r0 + r) * 128 + c];
        else         v = g_ctr2[(b * M2_ + r0 + r) * 2 + (c - 128)];
        sh[r][c] = v;
    }
    __syncthreads();
    float acc[64];
#pragma unroll
    for (int r = 0; r < 64; r++) acc[r] = 0.0f;
    for (int c = 0; c < 130; c++) {
        float w = W[c * 1024 + f];
#pragma unroll
        for (int r = 0; r < 64; r++) acc[r] = fmaf(sh[r][c], w, acc[r]);
    }
    float mx = acc[0];
#pragma unroll
    for (int r = 1; r < 64; r++) mx = fmaxf(mx, acc[r]);
    g_pmax[(b * 8 + rchunk) * 1024 + f] = mx + bias[f];
}

__global__ void final_reduce(float* __restrict__ gf) {
    int b = blockIdx.x, f = threadIdx.x;  // 1024
    float mx = g_pmax[(b * 8) * 1024 + f];
#pragma unroll
    for (int r = 1; r < 8; r++) mx = fmaxf(mx, g_pmax[(b * 8 + r) * 1024 + f]);
    gf[b * 1024 + f] = mx;
}

// ---------------- launch ---------------------------------------------------
extern "C" void kernel_launch(void* const* d_in, const int* in_sizes, int n_in,
                              void* d_out, int out_size) {
    const float* x     = (const float*)d_in[0];
    const float* zones = (const float*)d_in[1];
    const float* lf_W1 = (const float*)d_in[2];
    const float* lf_b1 = (const float*)d_in[3];
    const float* lf_W2 = (const float*)d_in[4];
    const float* lf_b2 = (const float*)d_in[5];
    const float* c1_W  = (const float*)d_in[6];
    const float* c1_b  = (const float*)d_in[7];
    const float* c2_W  = (const float*)d_in[8];
    const float* c2_b  = (const float*)d_in[9];
    const float* c3_W  = (const float*)d_in[10];
    const float* c3_b  = (const float*)d_in[11];

    float* lf_out = (float*)d_out;
    float* gf_out = (float*)d_out + (size_t)B_ * N_ * LF_;

    fps1_lfp1_kernel<<<B_ + 16, 1024>>>(x, zones, lf_W1, lf_b1, lf_W2, lf_b2,
                                        c1_W, c1_b, lf_out);
    fps2_sa1_kernel<<<B_ + B_ * M1_, 512>>>(c1_W, c2_W, c2_b);
    sa2_kernel<<<dim3(M2_, B_), F2_>>>(c2_W);
    final_partial<<<dim3(8, 8, B_), 128>>>(c3_W, c3_b);
    final_reduce<<<B_, 1024>>>(gf_out);
}

// round 17
// speedup vs baseline: 1.4782x; 1.0589x over previous
#include <cuda_runtime.h>
#include <cuda_bf16.h>
#include <cstdint>

#define B_  4
#define N_  4096
#define M1_ 2048
#define M2_ 512
#define F1_ 64
#define F2_ 128
#define F3_ 1024
#define LF_ 64
#define MAXNBR 128

#define GRID_LO   (-18.0f)
#define GRID_INV  (16.0f / 36.0f)

// ---------------- device scratch ----------------
__device__ float g_p1  [B_ * N_  * F1_];
__device__ float g_ctr1[B_ * M1_ * 2];
__device__ float g_p2  [B_ * M1_ * F2_];
__device__ float g_h2  [B_ * M2_ * F2_];
__device__ float g_ctr2[B_ * M2_ * 2];
__device__ float g_pmax[B_ * 16 * F3_];
// exported bucket sort (level 0: x points, level 1: ctr1 points)
__device__ float2         g_sxy2[2][B_][N_];
__device__ unsigned short g_sil[2][B_][N_];
__device__ int            g_cel[2][B_][256];

// ================= FUSED LAUNCH 1: FPS level-1 (blocks 0-3) + lfp1 (4-19) ==
__global__ __launch_bounds__(1024, 1) void fps1_lfp1_kernel(
    const float* __restrict__ x, const float* __restrict__ zones,
    const float* __restrict__ W1, const float* __restrict__ b1,
    const float* __restrict__ W2, const float* __restrict__ b2,
    const float* __restrict__ c1W, const float* __restrict__ c1b,
    float* __restrict__ lf_out) {
    const int T = 1024, P = 4, N = N_, M = M1_;
    const unsigned FULL = 0xFFFFFFFFu;
    int tid = threadIdx.x;

    __shared__ float2 sxy[N];
    __shared__ float spx[N], spy[N];
    __shared__ unsigned short ssidx[N];
    __shared__ int counts[256], offs[256], cursor[256];
    __shared__ float          sVv[2][32];
    __shared__ unsigned short sVi[2][32];

    if (blockIdx.x >= B_) {
        // ---------------- lfp1 branch (aliases FPS smem) ----------------
        float* sW2 = spx;
        float* sWc = (float*)sxy;
        float* sW1 = spy;
        float* sb1 = spy + 128;
        float* sb2 = spy + 192;
        float* sbc = spy + 256;
        float* st1 = (float*)ssidx;
        float* slf = ((float*)ssidx) + 1024;
        int grp = tid >> 6;
        int gt  = tid & 63;
        for (int i = tid; i < 64 * 64; i += 1024) sW2[i] = W2[i];
        for (int i = tid; i < 65 * 64; i += 1024) sWc[i] = c1W[i];
        if (tid < 128) sW1[tid] = W1[tid];
        if (tid < 64) { sb1[tid] = b1[tid]; sb2[tid] = b2[tid]; sbc[tid] = c1b[tid]; }
        __syncthreads();
        int row0 = (blockIdx.x - B_) * 1024 + grp * 64;
        float* myt1 = st1 + grp * 64;
        float* mylf = slf + grp * 64;
        for (int r = 0; r < 64; r++) {
            int row = row0 + r;
            float x0 = x[row * 2], x1 = x[row * 2 + 1];
            float t1 = tanhf(x0 * sW1[gt] + x1 * sW1[64 + gt] + sb1[gt]);
            myt1[gt] = t1;
            __syncthreads();
            float acc = sb2[gt];
#pragma unroll
            for (int c = 0; c < 64; c++) acc = fmaf(myt1[c], sW2[c * 64 + gt], acc);
            float lf = tanhf(acc);
            lf_out[row * 64 + gt] = lf;
            mylf[gt] = lf;
            __syncthreads();
            float z = zones[row];
            float acc2 = fmaf(z, sWc[64 * 64 + gt], sbc[gt]);
#pragma unroll
            for (int c = 0; c < 64; c++) acc2 = fmaf(mylf[c], sWc[c * 64 + gt], acc2);
            g_p1[row * 64 + gt] = acc2;
            __syncthreads();
        }
        return;
    }

    // ---------------- FPS level-1 branch (R13 form) ----------------
    int b = blockIdx.x;
    int wid = tid >> 5, lane = tid & 31;
    const float2* p = (const float2*)(x + (size_t)b * N * 2);
    float* cout = g_ctr1 + (size_t)b * M * 2;

    float rx[P], ry[P];
    int cid[P];
#pragma unroll
    for (int k = 0; k < P; k++) {
        float2 v = p[tid + k * T];
        rx[k] = v.x; ry[k] = v.y;
        sxy[tid + k * T] = v;
    }
    if (tid < 256) counts[tid] = 0;
    if (tid < 64) { sVv[tid >> 5][tid & 31] = 0.0f; sVi[tid >> 5][tid & 31] = 0xFFFFu; }
    __syncthreads();
#pragma unroll
    for (int k = 0; k < P; k++) {
        int cx = (int)fminf(fmaxf((rx[k] - GRID_LO) * GRID_INV, 0.f), 15.f);
        int cy = (int)fminf(fmaxf((ry[k] - GRID_LO) * GRID_INV, 0.f), 15.f);
        cid[k] = cy * 16 + cx;
        atomicAdd(&counts[cid[k]], 1);
    }
    __syncthreads();
    if (tid < 256) offs[tid] = counts[tid];
    __syncthreads();
    for (int d = 1; d < 256; d <<= 1) {
        int v = 0;
        if (tid < 256 && tid >= d) v = offs[tid - d];
        __syncthreads();
        if (tid < 256 && tid >= d) offs[tid] += v;
        __syncthreads();
    }
    if (tid < 256) cursor[tid] = offs[tid] - counts[tid];
    __syncthreads();
#pragma unroll
    for (int k = 0; k < P; k++) {
        int pos = atomicAdd(&cursor[cid[k]], 1);
        spx[pos] = rx[k]; spy[pos] = ry[k];
        ssidx[pos] = (unsigned short)(tid + k * T);
    }
    __syncthreads();

    for (int i = tid; i < N; i += T) {
        g_sxy2[0][b][i] = make_float2(spx[i], spy[i]);
        g_sil[0][b][i] = ssidx[i];
    }
    if (tid < 256) g_cel[0][b][tid] = offs[tid];

    float px[P], py[P], md[P];
    unsigned sidx[P];
    float bx0 = 1e30f, bx1 = -1e30f, by0 = 1e30f, by1 = -1e30f;
    int base = tid * P;
#pragma unroll
    for (int k = 0; k < P; k++) {
        px[k] = spx[base + k]; py[k] = spy[base + k];
        sidx[k] = (unsigned)ssidx[base + k];
        md[k] = 1e10f;
        bx0 = fminf(bx0, px[k]); bx1 = fmaxf(bx1, px[k]);
        by0 = fminf(by0, py[k]); by1 = fmaxf(by1, py[k]);
    }
#pragma unroll
    for (int o = 16; o > 0; o >>= 1) {
        bx0 = fminf(bx0, __shfl_xor_sync(FULL, bx0, o));
        bx1 = fmaxf(bx1, __shfl_xor_sync(FULL, bx1, o));
        by0 = fminf(by0, __shfl_xor_sync(FULL, by0, o));
        by1 = fmaxf(by1, __shfl_xor_sync(FULL, by1, o));
    }
    __syncthreads();

    float2 c0 = sxy[0];
    float lx = c0.x, ly = c0.y;
    if (tid == 0) { cout[0] = lx; cout[1] = ly; }

    float wvf = 1e10f;
    unsigned wi_ = 0u;

    for (int t = 1; t < M; t++) {
        float ex = fmaxf(fmaxf(bx0 - lx, lx - bx1), 0.f);
        float ey = fmaxf(fmaxf(by0 - ly, ly - by1), 0.f);
        float lb = fmaf(ex, ex, ey * ey);
        if (lb < wvf) {
            float tb = -1.f;
#pragma unroll
            for (int k = 0; k < P; k++) {
                float dx = px[k] - lx, dy = py[k] - ly;
                float d2 = fmaf(dx, dx, dy * dy);
                md[k] = fminf(md[k], d2);
                tb = fmaxf(tb, md[k]);
            }
            unsigned bi = 0xFFFFFFFFu;
#pragma unroll
            for (int k = 0; k < P; k++)
                if (md[k] == tb && sidx[k] < bi) bi = sidx[k];
            unsigned vb = __float_as_uint(tb);
            unsigned wm = __reduce_max_sync(FULL, vb);
            unsigned cand = (vb == wm) ? bi : 0xFFFFFFFFu;
            wi_ = __reduce_min_sync(FULL, cand);
            wvf = __uint_as_float(wm);
        }
        int buf = t & 1;
        if (lane == 0) {
            sVv[buf][wid] = wvf;
            sVi[buf][wid] = (unsigned short)wi_;
        }
        __syncthreads();
        float v2f = sVv[buf][lane];
        unsigned i2 = (unsigned)sVi[buf][lane];
        unsigned v2 = __float_as_uint(v2f);
        unsigned m2 = __reduce_max_sync(FULL, v2);
        unsigned c2 = (v2 == m2) ? i2 : 0xFFFFFFFFu;
        unsigned gi = __reduce_min_sync(FULL, c2);
        float2 w = sxy[gi];
        lx = w.x; ly = w.y;
        if (tid == 0) { cout[t * 2] = lx; cout[t * 2 + 1] = ly; }
    }
}

// ===== FUSED LAUNCH 2: FPS level-2 (blocks 0-3) + sa1+p2 (4..4+B*M1) ======
__global__ __launch_bounds__(512, 1) void fps2_sa1_kernel(
    const float* __restrict__ c1W,
    const float* __restrict__ c2W, const float* __restrict__ c2b) {
    const unsigned FULL = 0xFFFFFFFFu;
    int tid = threadIdx.x;

    __shared__ __align__(16) unsigned char sraw[40320];

    if (blockIdx.x >= B_) {
        // ---------------- sa1 + p2 branch ----------------
        float* sW   = (float*)sraw;
        float* sb   = (float*)(sraw + 32768);
        float* h1s  = (float*)(sraw + 33280);
        float* sdx  = (float*)(sraw + 33536);
        float* sdy  = (float*)(sraw + 34048);
        int*   snb  = (int*)(sraw + 34560);
        int*   scnt = (int*)(sraw + 35072);

        const int M = M1_, F = F1_;
        const float R = 0.5f, R2 = 0.25f;
        int idx = blockIdx.x - B_;
        int i = idx & (M1_ - 1);
        int b = idx >> 11;
        for (int k = tid; k < 64 * 128; k += 512) sW[k] = c2W[k];
        if (tid < 128) sb[tid] = c2b[tid];
        if (tid == 0) *scnt = 0;
        __syncthreads();
        float cx = g_ctr1[(b * M + i) * 2], cy = g_ctr1[(b * M + i) * 2 + 1];
        int ix0 = max(0, (int)((cx - R - GRID_LO) * GRID_INV));
        int ix1 = min(15, (int)((cx + R - GRID_LO) * GRID_INV));
        int iy0 = max(0, (int)((cy - R - GRID_LO) * GRID_INV));
        int iy1 = min(15, (int)((cy + R - GRID_LO) * GRID_INV));
        for (int gy = iy0; gy <= iy1; gy++) {
            int c0 = gy * 16 + ix0, c1 = gy * 16 + ix1;
            int s = (c0 == 0) ? 0 : g_cel[0][b][c0 - 1];
            int e = g_cel[0][b][c1];
            for (int j = s + tid; j < e; j += 512) {
                float2 pj = g_sxy2[0][b][j];
                float dx = pj.x - cx, dy = pj.y - cy;
                float d2 = fmaf(dx, dx, dy * dy);
                if (d2 <= R2) {
                    int s2 = atomicAdd(scnt, 1);
                    if (s2 < MAXNBR) {
                        snb[s2] = (int)g_sil[0][b][j];
                        sdx[s2] = dx; sdy[s2] = dy;
                    }
                }
            }
        }
        __syncthreads();
        int cnt = min(*scnt, MAXNBR);
        if (tid < F) {
            float wx = c1W[65 * 64 + tid];
            float wy = c1W[66 * 64 + tid];
            float mx = -1e9f;
            const float* pb = g_p1 + (size_t)b * N_ * F;
            int n = 0;
            for (; n + 4 <= cnt; n += 4) {
                float v0 = pb[snb[n] * F + tid];
                float v1 = pb[snb[n + 1] * F + tid];
                float v2 = pb[snb[n + 2] * F + tid];
                float v3 = pb[snb[n + 3] * F + tid];
                float m0 = fmaf(sdx[n], wx, fmaf(sdy[n], wy, v0));
                float m1 = fmaf(sdx[n + 1], wx, fmaf(sdy[n + 1], wy, v1));
                float m2 = fmaf(sdx[n + 2], wx, fmaf(sdy[n + 2], wy, v2));
                float m3 = fmaf(sdx[n + 3], wx, fmaf(sdy[n + 3], wy, v3));
                mx = fmaxf(mx, fmaxf(fmaxf(m0, m1), fmaxf(m2, m3)));
            }
            for (; n < cnt; n++) {
                float m = fmaf(sdx[n], wx, fmaf(sdy[n], wy, pb[snb[n] * F + tid]));
                mx = fmaxf(mx, m);
            }
            h1s[tid] = mx;
        }
        __syncthreads();
        if (tid < 128) {
            float acc = sb[tid];
#pragma unroll
            for (int c = 0; c < 64; c++) acc = fmaf(h1s[c], sW[c * 128 + tid], acc);
            g_p2[((size_t)b * M + i) * 128 + tid] = acc;
        }
        return;
    }

    // ---------------- FPS level-2 branch (R13 form) ----------------
    const int T = 512, P = 4, N = M1_, M = M2_;
    float2* sxy = (float2*)sraw;
    float*  spx = (float*)(sraw + 16384);
    float*  spy = (float*)(sraw + 24576);
    unsigned short* ssidx = (unsigned short*)(sraw + 32768);
    int* counts = (int*)(sraw + 36864);
    int* offs   = (int*)(sraw + 37888);
    float*          sVv = (float*)(sraw + 38912);
    unsigned short* sVi = (unsigned short*)(sraw + 39168);
    int* cursor = (int*)(sraw + 39296);

    int b = blockIdx.x;
    int wid = tid >> 5, lane = tid & 31;
    const float2* p = (const float2*)(g_ctr1 + (size_t)b * N * 2);
    float* cout = g_ctr2 + (size_t)b * M * 2;

    float rx[P], ry[P];
    int cid[P];
#pragma unroll
    for (int k = 0; k < P; k++) {
        float2 v = p[tid + k * T];
        rx[k] = v.x; ry[k] = v.y;
        sxy[tid + k * T] = v;
    }
    if (tid < 256) counts[tid] = 0;
    if (tid < 64) { sVv[tid] = 0.0f; sVi[tid] = 0xFFFFu; }
    __syncthreads();
#pragma unroll
    for (int k = 0; k < P; k++) {
        int cx = (int)fminf(fmaxf((rx[k] - GRID_LO) * GRID_INV, 0.f), 15.f);
        int cy = (int)fminf(fmaxf((ry[k] - GRID_LO) * GRID_INV, 0.f), 15.f);
        cid[k] = cy * 16 + cx;
        atomicAdd(&counts[cid[k]], 1);
    }
    __syncthreads();
    if (tid < 256) offs[tid] = counts[tid];
    __syncthreads();
    for (int d = 1; d < 256; d <<= 1) {
        int v = 0;
        if (tid < 256 && tid >= d) v = offs[tid - d];
        __syncthreads();
        if (tid < 256 && tid >= d) offs[tid] += v;
        __syncthreads();
    }
    if (tid < 256) cursor[tid] = offs[tid] - counts[tid];
    __syncthreads();
#pragma unroll
    for (int k = 0; k < P; k++) {
        int pos = atomicAdd(&cursor[cid[k]], 1);
        spx[pos] = rx[k]; spy[pos] = ry[k];
        ssidx[pos] = (unsigned short)(tid + k * T);
    }
    __syncthreads();

    for (int i = tid; i < N; i += T) {
        g_sxy2[1][b][i] = make_float2(spx[i], spy[i]);
        g_sil[1][b][i] = ssidx[i];
    }
    if (tid < 256) g_cel[1][b][tid] = offs[tid];

    float px[P], py[P], md[P];
    unsigned sidx[P];
    float bx0 = 1e30f, bx1 = -1e30f, by0 = 1e30f, by1 = -1e30f;
    int base = tid * P;
#pragma unroll
    for (int k = 0; k < P; k++) {
        px[k] = spx[base + k]; py[k] = spy[base + k];
        sidx[k] = (unsigned)ssidx[base + k];
        md[k] = 1e10f;
        bx0 = fminf(bx0, px[k]); bx1 = fmaxf(bx1, px[k]);
        by0 = fminf(by0, py[k]); by1 = fmaxf(by1, py[k]);
    }
#pragma unroll
    for (int o = 16; o > 0; o >>= 1) {
        bx0 = fminf(bx0, __shfl_xor_sync(FULL, bx0, o));
        bx1 = fmaxf(bx1, __shfl_xor_sync(FULL, bx1, o));
        by0 = fminf(by0, __shfl_xor_sync(FULL, by0, o));
        by1 = fmaxf(by1, __shfl_xor_sync(FULL, by1, o));
    }
    __syncthreads();

    float2 c0 = sxy[0];
    float lx = c0.x, ly = c0.y;
    if (tid == 0) { cout[0] = lx; cout[1] = ly; }

    float wvf = 1e10f;
    unsigned wi_ = 0u;

    for (int t = 1; t < M; t++) {
        float ex = fmaxf(fmaxf(bx0 - lx, lx - bx1), 0.f);
        float ey = fmaxf(fmaxf(by0 - ly, ly - by1), 0.f);
        float lb = fmaf(ex, ex, ey * ey);
        if (lb < wvf) {
            float tb = -1.f;
#pragma unroll
            for (int k = 0; k < P; k++) {
                float dx = px[k] - lx, dy = py[k] - ly;
                float d2 = fmaf(dx, dx, dy * dy);
                md[k] = fminf(md[k], d2);
                tb = fmaxf(tb, md[k]);
            }
            unsigned bi = 0xFFFFFFFFu;
#pragma unroll
            for (int k = 0; k < P; k++)
                if (md[k] == tb && sidx[k] < bi) bi = sidx[k];
            unsigned vb = __float_as_uint(tb);
            unsigned wm = __reduce_max_sync(FULL, vb);
            unsigned cand = (vb == wm) ? bi : 0xFFFFFFFFu;
            wi_ = __reduce_min_sync(FULL, cand);
            wvf = __uint_as_float(wm);
        }
        int buf = t & 1;
        if (lane == 0) {
            sVv[buf * 32 + wid] = wvf;
            sVi[buf * 32 + wid] = (unsigned short)wi_;
        }
        __syncthreads();
        float v2f = sVv[buf * 32 + lane];
        unsigned i2 = (unsigned)sVi[buf * 32 + lane];
        unsigned v2 = __float_as_uint(v2f);
        unsigned m2 = __reduce_max_sync(FULL, v2);
        unsigned c2 = (v2 == m2) ? i2 : 0xFFFFFFFFu;
        unsigned gi = __reduce_min_sync(FULL, c2);
        float2 w = sxy[gi];
        lx = w.x; ly = w.y;
        if (tid == 0) { cout[t * 2] = lx; cout[t * 2 + 1] = ly; }
    }
}

// ---------------- SA2: grid-pruned (r=1.0 over ctr1 via FPS2's sort) ------
__global__ void sa2_kernel(const float* __restrict__ c2W) {
    const int M = M2_, F = F2_;
    const float R = 1.0f, R2 = 1.0f;
    int i = blockIdx.x, b = blockIdx.y, tid = threadIdx.x;  // 128
    __shared__ float sdx[MAXNBR], sdy[MAXNBR];
    __shared__ int   snb[MAXNBR];
    __shared__ int   scnt;
    if (tid == 0) scnt = 0;
    __syncthreads();
    float cx = g_ctr2[(b * M + i) * 2], cy = g_ctr2[(b * M + i) * 2 + 1];
    int ix0 = max(0, (int)((cx - R - GRID_LO) * GRID_INV));
    int ix1 = min(15, (int)((cx + R - GRID_LO) * GRID_INV));
    int iy0 = max(0, (int)((cy - R - GRID_LO) * GRID_INV));
    int iy1 = min(15, (int)((cy + R - GRID_LO) * GRID_INV));
    for (int gy = iy0; gy <= iy1; gy++) {
        int c0 = gy * 16 + ix0, c1 = gy * 16 + ix1;
        int s = (c0 == 0) ? 0 : g_cel[1][b][c0 - 1];
        int e = g_cel[1][b][c1];
        for (int j = s + tid; j < e; j += F) {
            float2 pj = g_sxy2[1][b][j];
            float dx = pj.x - cx, dy = pj.y - cy;
            float d2 = fmaf(dx, dx, dy * dy);
            if (d2 <= R2) {
                int s2 = atomicAdd(&scnt, 1);
                if (s2 < MAXNBR) {
                    snb[s2] = (int)g_sil[1][b][j];
                    sdx[s2] = dx; sdy[s2] = dy;
                }
            }
        }
    }
    __syncthreads();
    int cnt = min(scnt, MAXNBR);
    float wx = c2W[64 * 128 + tid];
    float wy = c2W[65 * 128 + tid];
    float mx = -1e9f;
    const float* pb = g_p2 + (size_t)b * M1_ * F;
    int n = 0;
    for (; n + 4 <= cnt; n += 4) {
        float v0 = pb[snb[n] * F + tid];
        float v1 = pb[snb[n + 1] * F + tid];
        float v2 = pb[snb[n + 2] * F + tid];
        float v3 = pb[snb[n + 3] * F + tid];
        float m0 = fmaf(sdx[n], wx, fmaf(sdy[n], wy, v0));
        float m1 = fmaf(sdx[n + 1], wx, fmaf(sdy[n + 1], wy, v1));
        float m2 = fmaf(sdx[n + 2], wx, fmaf(sdy[n + 2], wy, v2));
        float m3 = fmaf(sdx[n + 3], wx, fmaf(sdy[n + 3], wy, v3));
        mx = fmaxf(mx, fmaxf(fmaxf(m0, m1), fmaxf(m2, m3)));
    }
    for (; n < cnt; n++) {
        float m = fmaf(sdx[n], wx, fmaf(sdy[n], wy, pb[snb[n] * F + tid]));
        mx = fmaxf(mx, m);
    }
    g_h2[((size_t)b * M + i) * F + tid] = mx;
}

// ------ final projection + partial max pool: 32 rows/block (NO spills) ----
__global__ void final_partial(const float* __restrict__ W, const float* __restrict__ bias) {
    int fchunk = blockIdx.x, rchunk = blockIdx.y, b = blockIdx.z;
    int tid = threadIdx.x;  // 128
    int f = fchunk * 128 + tid;
    __shared__ float sh[32][132];
    int r0 = rchunk * 32;
    for (int e = tid; e < 32 * 130; e += 128) {
        int r = e / 130, c = e % 130;
        float v;
        if (c < 128) v = g_h2[((size_t)b * M2_ + r0 + r) * 128 + c];
        else         v = g_ctr2[(b * M2_ + r0 + r) * 2 + (c - 128)];
        sh[r][c] = v;
    }
    __syncthreads();
    float acc[32];
#pragma unroll
    for (int r = 0; r < 32; r++) acc[r] = 0.0f;
    for (int c = 0; c < 130; c++) {
        float w = W[c * 1024 + f];
#pragma unroll
        for (int r = 0; r < 32; r++) acc[r] = fmaf(sh[r][c], w, acc[r]);
    }
    float mx = acc[0];
#pragma unroll
    for (int r = 1; r < 32; r++) mx = fmaxf(mx, acc[r]);
    g_pmax[(b * 16 + rchunk) * 1024 + f] = mx + bias[f];
}

__global__ void final_reduce(float* __restrict__ gf) {
    int b = blockIdx.x, f = threadIdx.x;  // 1024
    float mx = g_pmax[(b * 16) * 1024 + f];
#pragma unroll
    for (int r = 1; r < 16; r++) mx = fmaxf(mx, g_pmax[(b * 16 + r) * 1024 + f]);
    gf[b * 1024 + f] = mx;
}

// ---------------- launch ---------------------------------------------------
extern "C" void kernel_launch(void* const* d_in, const int* in_sizes, int n_in,
                              void* d_out, int out_size) {
    const float* x     = (const float*)d_in[0];
    const float* zones = (const float*)d_in[1];
    const float* lf_W1 = (const float*)d_in[2];
    const float* lf_b1 = (const float*)d_in[3];
    const float* lf_W2 = (const float*)d_in[4];
    const float* lf_b2 = (const float*)d_in[5];
    const float* c1_W  = (const float*)d_in[6];
    const float* c1_b  = (const float*)d_in[7];
    const float* c2_W  = (const float*)d_in[8];
    const float* c2_b  = (const float*)d_in[9];
    const float* c3_W  = (const float*)d_in[10];
    const float* c3_b  = (const float*)d_in[11];

    float* lf_out = (float*)d_out;
    float* gf_out = (float*)d_out + (size_t)B_ * N_ * LF_;

    fps1_lfp1_kernel<<<B_ + 16, 1024>>>(x, zones, lf_W1, lf_b1, lf_W2, lf_b2,
                                        c1_W, c1_b, lf_out);
    fps2_sa1_kernel<<<B_ + B_ * M1_, 512>>>(c1_W, c2_W, c2_b);
    sa2_kernel<<<dim3(M2_, B_), F2_>>>(c2_W);
    final_partial<<<dim3(8, 16, B_), 128>>>(c3_W, c3_b);
    final_reduce<<<B_, 1024>>>(gf_out);
}